// round 12
// baseline (speedup 1.0000x reference)
#include <cuda_runtime.h>
#include <cuda_fp16.h>
#include <math.h>
#include <stdint.h>

constexpr int N = 2048, E = 5, C = 2, W_IN = 256, W_OUT = 128, NUM_CLASS = 8, NT = 1024;
constexpr size_t NN = (size_t)N * (size_t)N;

// ---------------- half scratch ----------------
constexpr size_t HO_A    = 0;            // a [C,N,N]
constexpr size_t HO_B    = 2 * NN;       // b [C,N,N]
constexpr size_t HO_A1   = 4 * NN;       // a1; in-place cinv1-row-scaled
constexpr size_t HO_H    = 6 * NN;       // H diag->0
constexpr size_t HO_H2   = 8 * NN;       // H2 diag->1
constexpr size_t HO_XW   = 10 * NN;                      // [N,128]
constexpr size_t HO_XCAT = HO_XW   + (size_t)N * 128;    // [N,256]
constexpr size_t HO_XCW  = HO_XCAT + (size_t)N * 256;    // [N,384]
constexpr size_t H_TOTAL = HO_XCW  + (size_t)N * 384;

// ---------------- float scratch ----------------
constexpr size_t FO_XOR  = 0;                             // [N,384]
constexpr size_t FO_CI1  = FO_XOR + (size_t)N * 384;      // [C,N]
constexpr size_t FO_CI2  = FO_CI1 + (size_t)C * N;        // [C,N]
constexpr size_t FO_CIS  = FO_CI2 + (size_t)C * N;        // [N]
constexpr size_t FO_COLP = FO_CIS + N;                    // [2,64,N]
constexpr size_t FO_SW   = FO_COLP + (size_t)2 * 64 * N;  // 30 (pad 32)
constexpr size_t FO_PR   = FO_SW + 32;                    // 512
constexpr size_t FO_PC   = FO_PR + 512;                   // 16
constexpr size_t FO_P    = FO_PC + 16;                    // split-K partials [4][N][384]
constexpr size_t F_TOTAL = FO_P + (size_t)4 * N * 384;

__device__ __align__(1024) __half g_h[H_TOTAL];
__device__ __align__(1024) float  g_f[F_TOTAL];

// ============================ helpers ============================
__device__ __forceinline__ uint32_t smem_u32(const void* p) {
    uint32_t a;
    asm("{ .reg .u64 t; cvta.to.shared.u64 t, %1; cvt.u32.u64 %0, t; }" : "=r"(a) : "l"(p));
    return a;
}
__device__ __forceinline__ void cpa16(uint32_t saddr, const void* g) {
    asm volatile("cp.async.cg.shared.global [%0], [%1], 16;" :: "r"(saddr), "l"(g));
}
#define CP_COMMIT() asm volatile("cp.async.commit_group;" ::: "memory")

__device__ __forceinline__ void ldsm_x4(uint32_t* r, uint32_t a) {
    asm volatile("ldmatrix.sync.aligned.m8n8.x4.shared.b16 {%0,%1,%2,%3}, [%4];"
        : "=r"(r[0]), "=r"(r[1]), "=r"(r[2]), "=r"(r[3]) : "r"(a));
}
__device__ __forceinline__ void ldsm_x4t(uint32_t* r, uint32_t a) {
    asm volatile("ldmatrix.sync.aligned.m8n8.x4.trans.shared.b16 {%0,%1,%2,%3}, [%4];"
        : "=r"(r[0]), "=r"(r[1]), "=r"(r[2]), "=r"(r[3]) : "r"(a));
}
__device__ __forceinline__ void mma16816(float* d, const uint32_t* a, const uint32_t* b) {
    asm volatile(
        "mma.sync.aligned.m16n8k16.row.col.f32.f16.f16.f32 "
        "{%0,%1,%2,%3}, {%4,%5,%6,%7}, {%8,%9}, {%0,%1,%2,%3};"
        : "+f"(d[0]), "+f"(d[1]), "+f"(d[2]), "+f"(d[3])
        : "r"(a[0]), "r"(a[1]), "r"(a[2]), "r"(a[3]), "r"(b[0]), "r"(b[1]));
}

// ============================ big square GEMM (128x128 blk, 4 warps of 64x64) ============================
// C[z][m][n] = sum_k A[z][m][k]*B[z][k][n]; K=N=2048. flags: 2=diag->0, 4=diag->1.
__global__ void __launch_bounds__(128, 2)
hgemm_big(const __half* __restrict__ A, const __half* __restrict__ B, __half* __restrict__ Cout,
          int flags) {
    extern __shared__ __half sm[];
    constexpr int A_H = 128 * 72;
    constexpr int B_H = 64 * 136;
    constexpr int STG = A_H + B_H;

    const int tid = threadIdx.x, lane = tid & 31, wid = tid >> 5;
    const int wm = wid >> 1, wn = wid & 1;
    const int m0 = blockIdx.y * 128, n0 = blockIdx.x * 128;
    const size_t zoff = (size_t)blockIdx.z * NN;
    A += zoff; B += zoff; Cout += zoff;
    const uint32_t sb = smem_u32(sm);

    float acc[4][8][4] = {};

    auto fill = [&](int s, int k0) {
        uint32_t sa = sb + (uint32_t)s * STG * 2;
        #pragma unroll
        for (int e = 0; e < 8; e++) {
            int c = tid + e * 128;                 // 1024 chunks: A 128 rows x 8
            int m = c >> 3, ch = c & 7;
            cpa16(sa + (m * 72 + ch * 8) * 2, A + (size_t)(m0 + m) * N + k0 + ch * 8);
        }
        uint32_t sbb = sa + A_H * 2;
        #pragma unroll
        for (int e = 0; e < 8; e++) {
            int c = tid + e * 128;                 // 1024 chunks: B 64 rows x 16
            int kk = c >> 4, ch = c & 15;
            cpa16(sbb + (kk * 136 + ch * 8) * 2, B + (size_t)(k0 + kk) * N + n0 + ch * 8);
        }
        CP_COMMIT();
    };

    constexpr int NIT = N / 64;                    // 32 slabs
    fill(0, 0);
    fill(1, 64);

    for (int j = 0; j < NIT; j++) {
        if (j + 1 < NIT) asm volatile("cp.async.wait_group 1;" ::: "memory");
        else             asm volatile("cp.async.wait_group 0;" ::: "memory");
        __syncthreads();
        if (j + 2 < NIT) fill((j + 2) % 3, (j + 2) * 64);
        uint32_t sa = sb + (uint32_t)(j % 3) * STG * 2;
        uint32_t sbs = sa + A_H * 2;
        #pragma unroll
        for (int ks = 0; ks < 4; ks++) {
            uint32_t af[4][4], bf[4][4];
            #pragma unroll
            for (int mt = 0; mt < 4; mt++) {
                int row = wm * 64 + mt * 16 + (lane & 7) + ((lane >> 3) & 1) * 8;
                int col = ks * 16 + (lane >> 4) * 8;
                ldsm_x4(af[mt], sa + (row * 72 + col) * 2);
            }
            #pragma unroll
            for (int np = 0; np < 4; np++) {
                int kr = ks * 16 + (lane & 7) + ((lane >> 3) & 1) * 8;
                int col = wn * 64 + np * 16 + (lane >> 4) * 8;
                ldsm_x4t(bf[np], sbs + (kr * 136 + col) * 2);
            }
            #pragma unroll
            for (int mt = 0; mt < 4; mt++)
                #pragma unroll
                for (int nt = 0; nt < 8; nt++)
                    mma16816(acc[mt][nt], af[mt], &bf[nt >> 1][(nt & 1) * 2]);
        }
    }

    #pragma unroll
    for (int mt = 0; mt < 4; mt++) {
        #pragma unroll
        for (int hf = 0; hf < 2; hf++) {
            int r = m0 + wm * 64 + mt * 16 + (lane >> 2) + hf * 8;
            #pragma unroll
            for (int nt = 0; nt < 8; nt++) {
                int cc = n0 + wn * 64 + nt * 8 + (lane & 3) * 2;
                float v0 = acc[mt][nt][hf * 2 + 0];
                float v1 = acc[mt][nt][hf * 2 + 1];
                if (flags & 2) { if (r == cc) v0 = 0.f; if (r == cc + 1) v1 = 0.f; }
                if (flags & 4) { if (r == cc) v0 = 1.f; if (r == cc + 1) v1 = 1.f; }
                *(__half2*)(Cout + (size_t)r * N + cc) = __floats2half2_rn(v0, v1);
            }
        }
    }
}

// ============================ TRANSA fp16 GEMM (split-K partials) ============================
// f32 partial per (z,split) written to pbuf + blockIdx.z*pstride; Aop = A[k][m].
// SUMZ: K-space spans 2 z-planes of A (B shared).
template <bool SUMZ>
__global__ void __launch_bounds__(256, 2)
hgemm_ta(const __half* __restrict__ A, const __half* __restrict__ B,
         int K, int lda, int ldb, size_t szA, int nsplit,
         float* __restrict__ pbuf, int ldp, size_t pstride) {
    extern __shared__ __half sm[];
    constexpr int A_H = 64 * 136;
    constexpr int B_H = 64 * 136;
    constexpr int STG = A_H + B_H;

    const int tid = threadIdx.x, lane = tid & 31, wid = tid >> 5;
    const int wm = wid >> 2, wn = wid & 3;
    const int m0 = blockIdx.y * 128, n0 = blockIdx.x * 128;
    const int z = blockIdx.z / nsplit;
    const int split = blockIdx.z % nsplit;
    if (!SUMZ) A += (size_t)z * szA;
    const uint32_t sb = smem_u32(sm);

    float acc[4][4][4] = {};

    const int total_slabs = (SUMZ ? 2 * K : K) / 64;
    const int nit = total_slabs / nsplit;
    const int start = split * nit;

    auto fillA = [&](int s, int g) {
        int zz = SUMZ ? (g * 64) / K : 0;
        int k0 = SUMZ ? (g * 64) % K : g * 64;
        uint32_t sa = sb + (uint32_t)s * STG * 2;
        const __half* Ap = SUMZ ? A + (size_t)zz * szA : A;
        #pragma unroll
        for (int e = 0; e < 4; e++) {
            int c = tid + e * 256;
            int kk = c >> 4, ch = c & 15;
            cpa16(sa + (kk * 136 + ch * 8) * 2, Ap + (size_t)(k0 + kk) * lda + m0 + ch * 8);
        }
        uint32_t sbb = sa + A_H * 2;
        #pragma unroll
        for (int e = 0; e < 4; e++) {
            int c = tid + e * 256;
            int kk = c >> 4, ch = c & 15;
            cpa16(sbb + (kk * 136 + ch * 8) * 2, B + (size_t)(k0 + kk) * ldb + n0 + ch * 8);
        }
        CP_COMMIT();
    };

    fillA(0, start);
    fillA(1, start + 1);

    for (int j = 0; j < nit; j++) {
        if (j + 1 < nit) asm volatile("cp.async.wait_group 1;" ::: "memory");
        else             asm volatile("cp.async.wait_group 0;" ::: "memory");
        __syncthreads();
        if (j + 2 < nit) fillA((j + 2) % 3, start + j + 2);
        uint32_t sa = sb + (uint32_t)(j % 3) * STG * 2;
        uint32_t sbs = sa + A_H * 2;
        #pragma unroll
        for (int ks = 0; ks < 4; ks++) {
            uint32_t af[4][4], bf[2][4];
            #pragma unroll
            for (int mt = 0; mt < 4; mt++) {
                int kr = ks * 16 + (lane & 7) + (lane >> 4) * 8;
                int mc = wm * 64 + mt * 16 + ((lane >> 3) & 1) * 8;
                ldsm_x4t(af[mt], sa + (kr * 136 + mc) * 2);
            }
            #pragma unroll
            for (int np = 0; np < 2; np++) {
                int kr = ks * 16 + (lane & 7) + ((lane >> 3) & 1) * 8;
                int col = wn * 32 + np * 16 + (lane >> 4) * 8;
                ldsm_x4t(bf[np], sbs + (kr * 136 + col) * 2);
            }
            #pragma unroll
            for (int mt = 0; mt < 4; mt++)
                #pragma unroll
                for (int nt = 0; nt < 4; nt++)
                    mma16816(acc[mt][nt], af[mt], &bf[nt >> 1][(nt & 1) * 2]);
        }
    }

    float* P = pbuf + (size_t)blockIdx.z * pstride;
    #pragma unroll
    for (int mt = 0; mt < 4; mt++)
        #pragma unroll
        for (int hf = 0; hf < 2; hf++) {
            int r = m0 + wm * 64 + mt * 16 + (lane >> 2) + hf * 8;
            #pragma unroll
            for (int nt = 0; nt < 4; nt++) {
                int cc = n0 + wn * 32 + nt * 8 + (lane & 3) * 2;
                *(float2*)(P + (size_t)r * ldp + cc) =
                    make_float2(acc[mt][nt][hf * 2], acc[mt][nt][hf * 2 + 1]);
            }
        }
}

// ============================ split-K combines ============================
__global__ void comb9_k(const float* __restrict__ P, const float* __restrict__ ci2,
                        __half* __restrict__ Xcat) {
    int c = threadIdx.x;
    int r = blockIdx.x;
    int z = blockIdx.y;
    size_t pi = (size_t)(z * 2) * N * 128 + (size_t)r * 128 + c;
    float v = P[pi] + P[pi + (size_t)N * 128];
    v = fmaxf(v * ci2[z * N + r], 0.f);
    Xcat[(size_t)r * 256 + z * 128 + c] = __float2half_rn(v);
}

__global__ void comb11_k(const float* __restrict__ P, const __half* __restrict__ Xcw,
                         const float* __restrict__ cis, float* __restrict__ Xor) {
    int c = blockIdx.y * 128 + threadIdx.x;
    int r = blockIdx.x;
    size_t i = (size_t)r * 384 + c;
    float s = 0.f;
    #pragma unroll
    for (int sp = 0; sp < 4; sp++) s += P[(size_t)sp * N * 384 + i];
    s -= __half2float(Xcw[i]);
    Xor[i] = s * cis[r];
}

// ============================ small kernels ============================
__global__ void softmax_init_k(const float* __restrict__ w0a, const float* __restrict__ w0b,
                               const float* __restrict__ w1a, float* __restrict__ sw,
                               float* __restrict__ out) {
    int r = threadIdx.x;
    if (r < 3 * C) {
        int t = r >> 1, c = r & 1;
        const float* src = (t == 0) ? w0a : (t == 1) ? w0b : w1a;
        src += c * E;
        float v[E]; float m = -1e30f;
        #pragma unroll
        for (int e = 0; e < E; e++) { v[e] = src[e]; m = fmaxf(m, v[e]); }
        float s = 0.f;
        #pragma unroll
        for (int e = 0; e < E; e++) { v[e] = expf(v[e] - m); s += v[e]; }
        #pragma unroll
        for (int e = 0; e < E; e++) {
            float q = v[e] / s;
            sw[t * (C * E) + c * E + e] = q;
            out[1 + NT * NUM_CLASS + t * (C * E) + c * E + e] = q;
        }
    }
}

__global__ void gtconv_k(const float* __restrict__ A, const float* __restrict__ sw,
                         __half* __restrict__ pa, __half* __restrict__ pb,
                         __half* __restrict__ pa1) {
    size_t t = (size_t)blockIdx.x * blockDim.x + threadIdx.x;
    if (t * 4 >= NN) return;
    float v[20];
    const float4* Ap = (const float4*)(A + t * 20);
    #pragma unroll
    for (int q = 0; q < 5; q++) {
        float4 f = Ap[q];
        v[q * 4 + 0] = f.x; v[q * 4 + 1] = f.y; v[q * 4 + 2] = f.z; v[q * 4 + 3] = f.w;
    }
    #pragma unroll
    for (int c = 0; c < C; c++) {
        __half ha[4], hb[4], h1[4];
        #pragma unroll
        for (int g = 0; g < 4; g++) {
            float sa = 0.f, sb = 0.f, s1 = 0.f;
            #pragma unroll
            for (int e = 0; e < E; e++) {
                float av = v[g * 5 + e];
                sa = fmaf(sw[c * E + e], av, sa);
                sb = fmaf(sw[C * E + c * E + e], av, sb);
                s1 = fmaf(sw[2 * C * E + c * E + e], av, s1);
            }
            ha[g] = __float2half_rn(sa);
            hb[g] = __float2half_rn(sb);
            h1[g] = __float2half_rn(s1);
        }
        *(uint2*)(pa + c * NN + t * 4) = *(uint2*)ha;
        *(uint2*)(pb + c * NN + t * 4) = *(uint2*)hb;
        *(uint2*)(pa1 + c * NN + t * 4) = *(uint2*)h1;
    }
}

// a1[z][row][col8..+8] *= cinv1[z][row]  (in place)
__global__ void scale_a1_k(__half* __restrict__ a1, const float* __restrict__ cinv1) {
    int c8 = threadIdx.x * 8;
    int row = blockIdx.y, z = blockIdx.z;
    size_t i = (size_t)z * NN + (size_t)row * N + c8;
    float sc = cinv1[z * N + row];
    uint4 raw = *(uint4*)(a1 + i);
    __half2* h = (__half2*)&raw;
    #pragma unroll
    for (int q = 0; q < 4; q++) {
        float2 f = __half22float2(h[q]);
        h[q] = __floats2half2_rn(f.x * sc, f.y * sc);
    }
    *(uint4*)(a1 + i) = raw;
}

// column partial sums over 32-row chunks, 8 cols per thread (uint4 loads)
__global__ void colsum_part_h(const __half* __restrict__ H, float* __restrict__ part, size_t sH) {
    int c8 = threadIdx.x * 8;
    const __half* p = H + (size_t)blockIdx.z * sH + (size_t)blockIdx.y * 32 * N + c8;
    float s[8] = {};
    #pragma unroll 4
    for (int i = 0; i < 32; i++) {
        uint4 raw = *(const uint4*)(p + (size_t)i * N);
        const __half2* h = (const __half2*)&raw;
        #pragma unroll
        for (int q = 0; q < 4; q++) {
            float2 f = __half22float2(h[q]);
            s[q * 2] += f.x; s[q * 2 + 1] += f.y;
        }
    }
    float* dst = part + ((size_t)blockIdx.z * 64 + blockIdx.y) * N + c8;
    *(float4*)dst = make_float4(s[0], s[1], s[2], s[3]);
    *(float4*)(dst + 4) = make_float4(s[4], s[5], s[6], s[7]);
}

__global__ void cinv_fin_k(const float* __restrict__ part, float* __restrict__ cinv) {
    int col = blockIdx.x * 256 + threadIdx.x;
    int z = blockIdx.z;
    float s = 0.f;
    #pragma unroll
    for (int r = 0; r < 64; r++) s += part[((size_t)z * 64 + r) * N + col];
    cinv[z * N + col] = (s == 0.f) ? 0.f : 1.f / s;
}

__global__ void fin2_k(const float* __restrict__ part, float* __restrict__ cinv2,
                       float* __restrict__ cinvs) {
    int col = blockIdx.x * 256 + threadIdx.x;
    float sz[2];
    #pragma unroll
    for (int z = 0; z < 2; z++) {
        float s = 0.f;
        #pragma unroll
        for (int r = 0; r < 64; r++) s += part[((size_t)z * 64 + r) * N + col];
        sz[z] = s;
        cinv2[z * N + col] = (s == 0.f) ? 0.f : 1.f / s;
    }
    float d = sz[0] + sz[1] - 1.f;
    cinvs[col] = (d == 0.f) ? 0.f : 1.f / d;
}

// SIMT GEMM, A generic (float/half), B float, out half (operands full precision)
template <typename TA, int BM, int BN, int BK, int TM, int TN>
__global__ __launch_bounds__((BM / TM) * (BN / TN))
void sgemm_k(const TA* __restrict__ A, const float* __restrict__ B, __half* __restrict__ Cp,
             int K, int lda, int ldb, int ldc) {
    constexpr int NTHREADS = (BM / TM) * (BN / TN);
    __shared__ float As[BK][BM];
    __shared__ float Bs[BK][BN];
    const int tid = threadIdx.x;
    const int m0 = blockIdx.y * BM, n0 = blockIdx.x * BN;
    constexpr int TX = BN / TN;
    const int tx = tid % TX, ty = tid / TX;
    float acc[TM][TN];
    #pragma unroll
    for (int i = 0; i < TM; i++)
        #pragma unroll
        for (int j = 0; j < TN; j++) acc[i][j] = 0.f;
    for (int k0 = 0; k0 < K; k0 += BK) {
        constexpr int NA = (BM * BK) / NTHREADS;
        #pragma unroll
        for (int e = 0; e < NA; e++) {
            int idx = tid + e * NTHREADS;
            int mm = idx / BK, kk = idx % BK;
            As[kk][mm] = (float)A[(size_t)(m0 + mm) * lda + k0 + kk];
        }
        constexpr int NB = (BN * BK) / (NTHREADS * 4);
        #pragma unroll
        for (int e = 0; e < NB; e++) {
            int idx = tid + e * NTHREADS;
            int kk = idx / (BN / 4), nv = idx % (BN / 4);
            float4 v = *(const float4*)(B + (size_t)(k0 + kk) * ldb + n0 + nv * 4);
            *(float4*)&Bs[kk][nv * 4] = v;
        }
        __syncthreads();
        #pragma unroll
        for (int kk = 0; kk < BK; kk++) {
            float ra[TM], rb[TN];
            #pragma unroll
            for (int i = 0; i < TM; i++) ra[i] = As[kk][ty * TM + i];
            #pragma unroll
            for (int j = 0; j < TN; j++) rb[j] = Bs[kk][tx * TN + j];
            #pragma unroll
            for (int i = 0; i < TM; i++)
                #pragma unroll
                for (int j = 0; j < TN; j++) acc[i][j] = fmaf(ra[i], rb[j], acc[i][j]);
        }
        __syncthreads();
    }
    #pragma unroll
    for (int i = 0; i < TM; i++)
        #pragma unroll
        for (int j = 0; j < TN; j++)
            Cp[(size_t)(m0 + ty * TM + i) * ldc + n0 + tx * TN + j] =
                __float2half_rn(acc[i][j]);
}

__global__ void y_k(const float* __restrict__ Xo, const float* __restrict__ lw,
                    const float* __restrict__ lb, const int* __restrict__ txp,
                    float* __restrict__ outy) {
    int id = blockIdx.x * blockDim.x + threadIdx.x;
    if (id >= NT * NUM_CLASS) return;
    int t = id / NUM_CLASS, k = id % NUM_CLASS;
    const float* xr = Xo + (size_t)txp[t] * 384;
    const float* wr = lw + (size_t)k * W_OUT;
    float s = 0.f;
    #pragma unroll 4
    for (int d = 0; d < W_OUT; d++) s = fmaf(xr[d], wr[d], s);
    outy[id] = s + lb[k];
}

__global__ void lossC_k(const float* __restrict__ y, const int* __restrict__ tgt,
                        float* __restrict__ part) {
    __shared__ float red[256];
    int t = blockIdx.x * 256 + threadIdx.x;
    float yv[NUM_CLASS];
    float m = -1e30f;
    #pragma unroll
    for (int k = 0; k < NUM_CLASS; k++) { yv[k] = y[t * NUM_CLASS + k]; m = fmaxf(m, yv[k]); }
    float se = 0.f;
    #pragma unroll
    for (int k = 0; k < NUM_CLASS; k++) se += expf(yv[k] - m);
    float lse = m + logf(se);
    red[threadIdx.x] = yv[tgt[t]] - lse;
    __syncthreads();
    for (int s = 128; s > 0; s >>= 1) {
        if (threadIdx.x < s) red[threadIdx.x] += red[threadIdx.x + s];
        __syncthreads();
    }
    if (threadIdx.x == 0) part[blockIdx.x] = red[0];
}

__global__ void lossR_k(const float* __restrict__ XORb, const float* __restrict__ X,
                        float* __restrict__ part) {
    __shared__ float red[256];
    const size_t total = (size_t)N * W_IN;
    size_t tid = (size_t)blockIdx.x * 256 + threadIdx.x;
    size_t stride = (size_t)gridDim.x * 256;
    float acc = 0.f;
    for (size_t i = tid; i < total; i += stride) {
        size_t row = i >> 8, col = i & 255;
        float x = XORb[row * 384 + 128 + col];
        if (x > 1.f || x < 0.f) x = 1.f / (1.f + expf(-x));
        float p = fminf(fmaxf(x, 1e-7f), 1.f - 1e-7f);
        float t = X[i];
        acc += t * logf(p) + (1.f - t) * log1pf(-p);
    }
    red[threadIdx.x] = acc;
    __syncthreads();
    for (int s = 128; s > 0; s >>= 1) {
        if (threadIdx.x < s) red[threadIdx.x] += red[threadIdx.x + s];
        __syncthreads();
    }
    if (threadIdx.x == 0) part[blockIdx.x] = red[0];
}

__global__ void final_k(const float* __restrict__ partR, const float* __restrict__ partC,
                        float* __restrict__ out) {
    __shared__ float red[256];
    red[threadIdx.x] = partR[threadIdx.x] + partR[threadIdx.x + 256];
    __syncthreads();
    for (int s = 128; s > 0; s >>= 1) {
        if (threadIdx.x < s) red[threadIdx.x] += red[threadIdx.x + s];
        __syncthreads();
    }
    if (threadIdx.x == 0) {
        float lossR = -red[0] / (float)((size_t)N * W_IN);
        float sC = partC[0] + partC[1] + partC[2] + partC[3];
        float lossC = -sC / (float)NT;
        out[0] = lossC + lossR;
        out[1 + NT * NUM_CLASS + 3 * C * E] = lossR;
    }
}

// ============================ host side ============================
constexpr int SMEM_BIG = (128 * 72 + 64 * 136) * 2 * 3;   // 107520
constexpr int SMEM_TA  = (64 * 136 + 64 * 136) * 2 * 3;   // 104448

extern "C" void kernel_launch(void* const* d_in, const int* in_sizes, int n_in,
                              void* d_out, int out_size) {
    __half* Hh = nullptr;
    float* S = nullptr;
    cudaGetSymbolAddress((void**)&Hh, g_h);
    cudaGetSymbolAddress((void**)&S, g_f);

    const float* A   = (const float*)d_in[0];
    const float* X   = (const float*)d_in[1];
    const float* W   = (const float*)d_in[2];
    const float* W1  = (const float*)d_in[3];
    const float* W2  = (const float*)d_in[4];
    const float* lw  = (const float*)d_in[5];
    const float* lb  = (const float*)d_in[6];
    const float* w0a = (const float*)d_in[7];
    const float* w0b = (const float*)d_in[8];
    const float* w1a = (const float*)d_in[9];
    const int* txp   = (const int*)d_in[10];
    const int* tgt   = (const int*)d_in[11];
    float* out = (float*)d_out;

    cudaFuncSetAttribute((const void*)hgemm_big,
                         cudaFuncAttributeMaxDynamicSharedMemorySize, SMEM_BIG);
    cudaFuncSetAttribute((const void*)hgemm_ta<false>,
                         cudaFuncAttributeMaxDynamicSharedMemorySize, SMEM_TA);
    cudaFuncSetAttribute((const void*)hgemm_ta<true>,
                         cudaFuncAttributeMaxDynamicSharedMemorySize, SMEM_TA);

    // 1. softmax weights + Ws outputs
    softmax_init_k<<<1, 32>>>(w0a, w0b, w1a, S + FO_SW, out);
    // 2. a, b, a1 (fp16)
    gtconv_k<<<(unsigned)(NN / 4 / 256), 256>>>(A, S + FO_SW, Hh + HO_A, Hh + HO_B, Hh + HO_A1);
    // 3. H = a @ b, diag->0
    hgemm_big<<<dim3(16, 16, 2), 128, SMEM_BIG>>>(Hh + HO_A, Hh + HO_B, Hh + HO_H, 2);
    // 4. cinv1 = 1/colsum(H)
    colsum_part_h<<<dim3(1, 64, 2), 256>>>(Hh + HO_H, S + FO_COLP, NN);
    cinv_fin_k<<<dim3(8, 1, 2), 256>>>(S + FO_COLP, S + FO_CI1);
    // 5. a1 <- diag(cinv1) @ a1  (in place)
    scale_a1_k<<<dim3(1, N, 2), 256>>>(Hh + HO_A1, S + FO_CI1);
    // 6. H2 = H @ a1n, diag->1
    hgemm_big<<<dim3(16, 16, 2), 128, SMEM_BIG>>>(Hh + HO_H, Hh + HO_A1, Hh + HO_H2, 4);
    // 7. cinv2, cinvs from H2 colsums  (cinvs = 1/(s0+s1-1))
    colsum_part_h<<<dim3(1, 64, 2), 256>>>(Hh + HO_H2, S + FO_COLP, NN);
    fin2_k<<<8, 256>>>(S + FO_COLP, S + FO_CI2, S + FO_CIS);
    // 8. XW = X @ W  (SIMT f32 operands, fp16 out)
    sgemm_k<float, 64, 64, 16, 4, 4><<<dim3(2, 32), 256>>>(X, W, Hh + HO_XW, W_IN, W_IN, 128, 128);
    // 9. P[z*2+s] = (H2[z]^T @ XW) k-split partials; combine -> Xcat
    hgemm_ta<false><<<dim3(1, 16, 4), 256, SMEM_TA>>>(
        Hh + HO_H2, Hh + HO_XW, N, N, 128, NN, 2, S + FO_P, 128, (size_t)N * 128);
    comb9_k<<<dim3(N, 2), 128>>>(S + FO_P, S + FO_CI2, Hh + HO_XCAT);
    // 10. Xcw = [Xcat@W1 | Xcat@W2]  (SIMT f32-B operands, fp16 out)
    sgemm_k<__half, 64, 64, 16, 4, 4><<<dim3(2, 32), 256>>>(
        Hh + HO_XCAT, W1, Hh + HO_XCW, 256, 256, 128, 384);
    sgemm_k<__half, 64, 64, 16, 4, 4><<<dim3(4, 32), 256>>>(
        Hh + HO_XCAT, W2, Hh + HO_XCW + 128, 256, 256, 256, 384);
    // 11. P[s] = partial sums of (sum_z H2[z]^T @ Xcw); combine -> Xor (f32)
    hgemm_ta<true><<<dim3(3, 16, 4), 256, SMEM_TA>>>(
        Hh + HO_H2, Hh + HO_XCW, N, N, 384, NN, 4, S + FO_P, 384, (size_t)N * 384);
    comb11_k<<<dim3(N, 3), 128>>>(S + FO_P, Hh + HO_XCW, S + FO_CIS, S + FO_XOR);
    // 12. y, losses, final
    y_k<<<(NT * NUM_CLASS) / 256, 256>>>(S + FO_XOR, lw, lb, txp, out + 1);
    lossC_k<<<NT / 256, 256>>>(out + 1, tgt, S + FO_PC);
    lossR_k<<<512, 256>>>(S + FO_XOR, X, S + FO_PR);
    final_k<<<1, 256>>>(S + FO_PR, S + FO_PC, out);
}

// round 13
// speedup vs baseline: 1.0982x; 1.0982x over previous
#include <cuda_runtime.h>
#include <cuda_fp16.h>
#include <math.h>
#include <stdint.h>

constexpr int N = 2048, E = 5, C = 2, W_IN = 256, W_OUT = 128, NUM_CLASS = 8, NT = 1024;
constexpr size_t NN = (size_t)N * (size_t)N;

// ---------------- half scratch ----------------
constexpr size_t HO_A    = 0;            // a [C,N,N]
constexpr size_t HO_B    = 2 * NN;       // b [C,N,N]
constexpr size_t HO_A1   = 4 * NN;       // a1; in-place cinv1-row-scaled
constexpr size_t HO_H    = 6 * NN;       // H diag->0
constexpr size_t HO_H2   = 8 * NN;       // H2 diag->1
constexpr size_t HO_XW   = 10 * NN;                      // [N,128]
constexpr size_t HO_XCAT = HO_XW   + (size_t)N * 128;    // [N,256]
constexpr size_t HO_XCW  = HO_XCAT + (size_t)N * 256;    // [N,384]
constexpr size_t HO_XHI  = HO_XCW  + (size_t)N * 384;    // X hi [N,256]
constexpr size_t HO_XLO  = HO_XHI  + (size_t)N * 256;    // X lo
constexpr size_t HO_WHI  = HO_XLO  + (size_t)N * 256;    // W hi [256,128]
constexpr size_t HO_WLO  = HO_WHI  + (size_t)256 * 128;
constexpr size_t HO_WFHI = HO_WLO  + (size_t)256 * 128;  // [W1|W2] hi [256,384]
constexpr size_t HO_WFLO = HO_WFHI + (size_t)256 * 384;
constexpr size_t H_TOTAL = HO_WFLO + (size_t)256 * 384;

// ---------------- float scratch ----------------
constexpr size_t FO_XOR  = 0;                             // [N,384]
constexpr size_t FO_CI1  = FO_XOR + (size_t)N * 384;      // [C,N]
constexpr size_t FO_CI2  = FO_CI1 + (size_t)C * N;        // [C,N]
constexpr size_t FO_CIS  = FO_CI2 + (size_t)C * N;        // [N]
constexpr size_t FO_COLP = FO_CIS + N;                    // [2,64,N]
constexpr size_t FO_SW   = FO_COLP + (size_t)2 * 64 * N;  // 30 (pad 32)
constexpr size_t FO_PR   = FO_SW + 32;                    // 512
constexpr size_t FO_PC   = FO_PR + 512;                   // 16
constexpr size_t FO_P    = FO_PC + 16;                    // split-K partials [4][N][384]
constexpr size_t F_TOTAL = FO_P + (size_t)4 * N * 384;

__device__ __align__(1024) __half g_h[H_TOTAL];
__device__ __align__(1024) float  g_f[F_TOTAL];

// ============================ helpers ============================
__device__ __forceinline__ uint32_t smem_u32(const void* p) {
    uint32_t a;
    asm("{ .reg .u64 t; cvta.to.shared.u64 t, %1; cvt.u32.u64 %0, t; }" : "=r"(a) : "l"(p));
    return a;
}
__device__ __forceinline__ void cpa16(uint32_t saddr, const void* g) {
    asm volatile("cp.async.cg.shared.global [%0], [%1], 16;" :: "r"(saddr), "l"(g));
}
#define CP_COMMIT() asm volatile("cp.async.commit_group;" ::: "memory")

__device__ __forceinline__ void ldsm_x4(uint32_t* r, uint32_t a) {
    asm volatile("ldmatrix.sync.aligned.m8n8.x4.shared.b16 {%0,%1,%2,%3}, [%4];"
        : "=r"(r[0]), "=r"(r[1]), "=r"(r[2]), "=r"(r[3]) : "r"(a));
}
__device__ __forceinline__ void ldsm_x4t(uint32_t* r, uint32_t a) {
    asm volatile("ldmatrix.sync.aligned.m8n8.x4.trans.shared.b16 {%0,%1,%2,%3}, [%4];"
        : "=r"(r[0]), "=r"(r[1]), "=r"(r[2]), "=r"(r[3]) : "r"(a));
}
__device__ __forceinline__ void mma16816(float* d, const uint32_t* a, const uint32_t* b) {
    asm volatile(
        "mma.sync.aligned.m16n8k16.row.col.f32.f16.f16.f32 "
        "{%0,%1,%2,%3}, {%4,%5,%6,%7}, {%8,%9}, {%0,%1,%2,%3};"
        : "+f"(d[0]), "+f"(d[1]), "+f"(d[2]), "+f"(d[3])
        : "r"(a[0]), "r"(a[1]), "r"(a[2]), "r"(a[3]), "r"(b[0]), "r"(b[1]));
}

// ============================ big square GEMM (128x128 blk, 4 warps of 64x64) ============================
// C[z][m][n] = sum_k A[z][m][k]*B[z][k][n]; K=N=2048. flags: 2=diag->0, 4=diag->1.
__global__ void __launch_bounds__(128, 2)
hgemm_big(const __half* __restrict__ A, const __half* __restrict__ B, __half* __restrict__ Cout,
          int flags) {
    extern __shared__ __half sm[];
    constexpr int A_H = 128 * 72;
    constexpr int B_H = 64 * 136;
    constexpr int STG = A_H + B_H;

    const int tid = threadIdx.x, lane = tid & 31, wid = tid >> 5;
    const int wm = wid >> 1, wn = wid & 1;
    const int m0 = blockIdx.y * 128, n0 = blockIdx.x * 128;
    const size_t zoff = (size_t)blockIdx.z * NN;
    A += zoff; B += zoff; Cout += zoff;
    const uint32_t sb = smem_u32(sm);

    float acc[4][8][4] = {};

    auto fill = [&](int s, int k0) {
        uint32_t sa = sb + (uint32_t)s * STG * 2;
        #pragma unroll
        for (int e = 0; e < 8; e++) {
            int c = tid + e * 128;
            int m = c >> 3, ch = c & 7;
            cpa16(sa + (m * 72 + ch * 8) * 2, A + (size_t)(m0 + m) * N + k0 + ch * 8);
        }
        uint32_t sbb = sa + A_H * 2;
        #pragma unroll
        for (int e = 0; e < 8; e++) {
            int c = tid + e * 128;
            int kk = c >> 4, ch = c & 15;
            cpa16(sbb + (kk * 136 + ch * 8) * 2, B + (size_t)(k0 + kk) * N + n0 + ch * 8);
        }
        CP_COMMIT();
    };

    constexpr int NIT = N / 64;
    fill(0, 0);
    fill(1, 64);

    for (int j = 0; j < NIT; j++) {
        if (j + 1 < NIT) asm volatile("cp.async.wait_group 1;" ::: "memory");
        else             asm volatile("cp.async.wait_group 0;" ::: "memory");
        __syncthreads();
        if (j + 2 < NIT) fill((j + 2) % 3, (j + 2) * 64);
        uint32_t sa = sb + (uint32_t)(j % 3) * STG * 2;
        uint32_t sbs = sa + A_H * 2;
        #pragma unroll
        for (int ks = 0; ks < 4; ks++) {
            uint32_t af[4][4], bf[4][4];
            #pragma unroll
            for (int mt = 0; mt < 4; mt++) {
                int row = wm * 64 + mt * 16 + (lane & 7) + ((lane >> 3) & 1) * 8;
                int col = ks * 16 + (lane >> 4) * 8;
                ldsm_x4(af[mt], sa + (row * 72 + col) * 2);
            }
            #pragma unroll
            for (int np = 0; np < 4; np++) {
                int kr = ks * 16 + (lane & 7) + ((lane >> 3) & 1) * 8;
                int col = wn * 64 + np * 16 + (lane >> 4) * 8;
                ldsm_x4t(bf[np], sbs + (kr * 136 + col) * 2);
            }
            #pragma unroll
            for (int mt = 0; mt < 4; mt++)
                #pragma unroll
                for (int nt = 0; nt < 8; nt++)
                    mma16816(acc[mt][nt], af[mt], &bf[nt >> 1][(nt & 1) * 2]);
        }
    }

    #pragma unroll
    for (int mt = 0; mt < 4; mt++) {
        #pragma unroll
        for (int hf = 0; hf < 2; hf++) {
            int r = m0 + wm * 64 + mt * 16 + (lane >> 2) + hf * 8;
            #pragma unroll
            for (int nt = 0; nt < 8; nt++) {
                int cc = n0 + wn * 64 + nt * 8 + (lane & 3) * 2;
                float v0 = acc[mt][nt][hf * 2 + 0];
                float v1 = acc[mt][nt][hf * 2 + 1];
                if (flags & 2) { if (r == cc) v0 = 0.f; if (r == cc + 1) v1 = 0.f; }
                if (flags & 4) { if (r == cc) v0 = 1.f; if (r == cc + 1) v1 = 1.f; }
                *(__half2*)(Cout + (size_t)r * N + cc) = __floats2half2_rn(v0, v1);
            }
        }
    }
}

// ============================ TRANSA fp16 GEMM (split-K partials) ============================
template <bool SUMZ>
__global__ void __launch_bounds__(256, 2)
hgemm_ta(const __half* __restrict__ A, const __half* __restrict__ B,
         int K, int lda, int ldb, size_t szA, int nsplit,
         float* __restrict__ pbuf, int ldp, size_t pstride) {
    extern __shared__ __half sm[];
    constexpr int A_H = 64 * 136;
    constexpr int B_H = 64 * 136;
    constexpr int STG = A_H + B_H;

    const int tid = threadIdx.x, lane = tid & 31, wid = tid >> 5;
    const int wm = wid >> 2, wn = wid & 3;
    const int m0 = blockIdx.y * 128, n0 = blockIdx.x * 128;
    const int z = blockIdx.z / nsplit;
    const int split = blockIdx.z % nsplit;
    if (!SUMZ) A += (size_t)z * szA;
    const uint32_t sb = smem_u32(sm);

    float acc[4][4][4] = {};

    const int total_slabs = (SUMZ ? 2 * K : K) / 64;
    const int nit = total_slabs / nsplit;
    const int start = split * nit;

    auto fillA = [&](int s, int g) {
        int zz = SUMZ ? (g * 64) / K : 0;
        int k0 = SUMZ ? (g * 64) % K : g * 64;
        uint32_t sa = sb + (uint32_t)s * STG * 2;
        const __half* Ap = SUMZ ? A + (size_t)zz * szA : A;
        #pragma unroll
        for (int e = 0; e < 4; e++) {
            int c = tid + e * 256;
            int kk = c >> 4, ch = c & 15;
            cpa16(sa + (kk * 136 + ch * 8) * 2, Ap + (size_t)(k0 + kk) * lda + m0 + ch * 8);
        }
        uint32_t sbb = sa + A_H * 2;
        #pragma unroll
        for (int e = 0; e < 4; e++) {
            int c = tid + e * 256;
            int kk = c >> 4, ch = c & 15;
            cpa16(sbb + (kk * 136 + ch * 8) * 2, B + (size_t)(k0 + kk) * ldb + n0 + ch * 8);
        }
        CP_COMMIT();
    };

    fillA(0, start);
    fillA(1, start + 1);

    for (int j = 0; j < nit; j++) {
        if (j + 1 < nit) asm volatile("cp.async.wait_group 1;" ::: "memory");
        else             asm volatile("cp.async.wait_group 0;" ::: "memory");
        __syncthreads();
        if (j + 2 < nit) fillA((j + 2) % 3, start + j + 2);
        uint32_t sa = sb + (uint32_t)(j % 3) * STG * 2;
        uint32_t sbs = sa + A_H * 2;
        #pragma unroll
        for (int ks = 0; ks < 4; ks++) {
            uint32_t af[4][4], bf[2][4];
            #pragma unroll
            for (int mt = 0; mt < 4; mt++) {
                int kr = ks * 16 + (lane & 7) + (lane >> 4) * 8;
                int mc = wm * 64 + mt * 16 + ((lane >> 3) & 1) * 8;
                ldsm_x4t(af[mt], sa + (kr * 136 + mc) * 2);
            }
            #pragma unroll
            for (int np = 0; np < 2; np++) {
                int kr = ks * 16 + (lane & 7) + ((lane >> 3) & 1) * 8;
                int col = wn * 32 + np * 16 + (lane >> 4) * 8;
                ldsm_x4t(bf[np], sbs + (kr * 136 + col) * 2);
            }
            #pragma unroll
            for (int mt = 0; mt < 4; mt++)
                #pragma unroll
                for (int nt = 0; nt < 4; nt++)
                    mma16816(acc[mt][nt], af[mt], &bf[nt >> 1][(nt & 1) * 2]);
        }
    }

    float* P = pbuf + (size_t)blockIdx.z * pstride;
    #pragma unroll
    for (int mt = 0; mt < 4; mt++)
        #pragma unroll
        for (int hf = 0; hf < 2; hf++) {
            int r = m0 + wm * 64 + mt * 16 + (lane >> 2) + hf * 8;
            #pragma unroll
            for (int nt = 0; nt < 4; nt++) {
                int cc = n0 + wn * 32 + nt * 8 + (lane & 3) * 2;
                *(float2*)(P + (size_t)r * ldp + cc) =
                    make_float2(acc[mt][nt][hf * 2], acc[mt][nt][hf * 2 + 1]);
            }
        }
}

// ============================ split-fp16 small GEMM (f32-accurate on tensor cores) ============================
// C = A @ B with A = Ah(+Al if ASPLIT), B = Bh+Bl (hi/lo fp16 split of f32 operands).
// acc += Ah@Bh + Ah@Bl (+ Al@Bh). Block 128x128, 8 warps (2m x 4n, 64x32 tiles), BK=64, 3-stage.
template <bool ASPLIT>
__global__ void __launch_bounds__(256)
hgemm_sp(const __half* __restrict__ Ah, const __half* __restrict__ Al,
         const __half* __restrict__ Bh, const __half* __restrict__ Bl,
         __half* __restrict__ Cout, int K, int lda, int ldb, int ldc) {
    extern __shared__ __half sm[];
    constexpr int A_SZ = 128 * 72;
    constexpr int B_SZ = 64 * 136;
    constexpr int A_TOT = ASPLIT ? 2 * A_SZ : A_SZ;
    constexpr int STG = A_TOT + 2 * B_SZ;

    const int tid = threadIdx.x, lane = tid & 31, wid = tid >> 5;
    const int wm = wid >> 2, wn = wid & 3;
    const int m0 = blockIdx.y * 128, n0 = blockIdx.x * 128;
    const uint32_t sb = smem_u32(sm);

    float acc[4][4][4] = {};

    auto fill = [&](int s, int k0) {
        uint32_t sa = sb + (uint32_t)s * STG * 2;
        #pragma unroll
        for (int e = 0; e < 4; e++) {
            int c = tid + e * 256;
            int m = c >> 3, ch = c & 7;
            cpa16(sa + (m * 72 + ch * 8) * 2, Ah + (size_t)(m0 + m) * lda + k0 + ch * 8);
        }
        if (ASPLIT) {
            uint32_t sal = sa + A_SZ * 2;
            #pragma unroll
            for (int e = 0; e < 4; e++) {
                int c = tid + e * 256;
                int m = c >> 3, ch = c & 7;
                cpa16(sal + (m * 72 + ch * 8) * 2, Al + (size_t)(m0 + m) * lda + k0 + ch * 8);
            }
        }
        uint32_t sbh = sa + A_TOT * 2;
        uint32_t sbl = sbh + B_SZ * 2;
        #pragma unroll
        for (int e = 0; e < 4; e++) {
            int c = tid + e * 256;
            int kk = c >> 4, ch = c & 15;
            cpa16(sbh + (kk * 136 + ch * 8) * 2, Bh + (size_t)(k0 + kk) * ldb + n0 + ch * 8);
            cpa16(sbl + (kk * 136 + ch * 8) * 2, Bl + (size_t)(k0 + kk) * ldb + n0 + ch * 8);
        }
        CP_COMMIT();
    };

    const int nit = K / 64;
    fill(0, 0);
    if (nit > 1) fill(1, 64);

    for (int j = 0; j < nit; j++) {
        if (j + 1 < nit) asm volatile("cp.async.wait_group 1;" ::: "memory");
        else             asm volatile("cp.async.wait_group 0;" ::: "memory");
        __syncthreads();
        if (j + 2 < nit) fill((j + 2) % 3, (j + 2) * 64);
        uint32_t sa = sb + (uint32_t)(j % 3) * STG * 2;
        uint32_t sbh = sa + A_TOT * 2;
        uint32_t sbl = sbh + B_SZ * 2;
        #pragma unroll
        for (int ks = 0; ks < 4; ks++) {
            uint32_t afh[4][4], afl[4][4], bfh[2][4], bfl[2][4];
            #pragma unroll
            for (int mt = 0; mt < 4; mt++) {
                int row = wm * 64 + mt * 16 + (lane & 7) + ((lane >> 3) & 1) * 8;
                int col = ks * 16 + (lane >> 4) * 8;
                ldsm_x4(afh[mt], sa + (row * 72 + col) * 2);
                if (ASPLIT) ldsm_x4(afl[mt], sa + (A_SZ + row * 72 + col) * 2);
            }
            #pragma unroll
            for (int np = 0; np < 2; np++) {
                int kr = ks * 16 + (lane & 7) + ((lane >> 3) & 1) * 8;
                int col = wn * 32 + np * 16 + (lane >> 4) * 8;
                ldsm_x4t(bfh[np], sbh + (kr * 136 + col) * 2);
                ldsm_x4t(bfl[np], sbl + (kr * 136 + col) * 2);
            }
            #pragma unroll
            for (int mt = 0; mt < 4; mt++)
                #pragma unroll
                for (int nt = 0; nt < 4; nt++) {
                    mma16816(acc[mt][nt], afh[mt], &bfh[nt >> 1][(nt & 1) * 2]);
                    mma16816(acc[mt][nt], afh[mt], &bfl[nt >> 1][(nt & 1) * 2]);
                    if (ASPLIT)
                        mma16816(acc[mt][nt], afl[mt], &bfh[nt >> 1][(nt & 1) * 2]);
                }
        }
    }

    #pragma unroll
    for (int mt = 0; mt < 4; mt++)
        #pragma unroll
        for (int hf = 0; hf < 2; hf++) {
            int r = m0 + wm * 64 + mt * 16 + (lane >> 2) + hf * 8;
            #pragma unroll
            for (int nt = 0; nt < 4; nt++) {
                int cc = n0 + wn * 32 + nt * 8 + (lane & 3) * 2;
                *(__half2*)(Cout + (size_t)r * ldc + cc) =
                    __floats2half2_rn(acc[mt][nt][hf * 2], acc[mt][nt][hf * 2 + 1]);
            }
        }
}

// ============================ split conversion ============================
// blocks [0,256): X -> Xhi/Xlo; [256,272): W -> Whi/Wlo; [272,320): W1|W2 -> Wfhi/Wflo
__global__ void split_all_k(const float* __restrict__ X, const float* __restrict__ W,
                            const float* __restrict__ W1, const float* __restrict__ W2,
                            __half* __restrict__ Xhi, __half* __restrict__ Xlo,
                            __half* __restrict__ Whi, __half* __restrict__ Wlo,
                            __half* __restrict__ Wfhi, __half* __restrict__ Wflo) {
    int b = blockIdx.x;
    __half hi[8], lo[8];
    if (b < 256) {
        size_t base = (size_t)b * 2048 + threadIdx.x * 8;
        #pragma unroll
        for (int q = 0; q < 8; q++) {
            float x = X[base + q];
            __half h = __float2half_rn(x);
            hi[q] = h;
            lo[q] = __float2half_rn(x - __half2float(h));
        }
        *(uint4*)(Xhi + base) = *(uint4*)hi;
        *(uint4*)(Xlo + base) = *(uint4*)lo;
    } else if (b < 272) {
        size_t base = (size_t)(b - 256) * 2048 + threadIdx.x * 8;
        #pragma unroll
        for (int q = 0; q < 8; q++) {
            float x = W[base + q];
            __half h = __float2half_rn(x);
            hi[q] = h;
            lo[q] = __float2half_rn(x - __half2float(h));
        }
        *(uint4*)(Whi + base) = *(uint4*)hi;
        *(uint4*)(Wlo + base) = *(uint4*)lo;
    } else {
        size_t base = (size_t)(b - 272) * 2048 + threadIdx.x * 8;
        int k = (int)(base / 384), c = (int)(base % 384);
        #pragma unroll
        for (int q = 0; q < 8; q++) {
            int cc = c + q;
            float x = (cc < 128) ? W1[k * 128 + cc] : W2[k * 256 + (cc - 128)];
            __half h = __float2half_rn(x);
            hi[q] = h;
            lo[q] = __float2half_rn(x - __half2float(h));
        }
        *(uint4*)(Wfhi + base) = *(uint4*)hi;
        *(uint4*)(Wflo + base) = *(uint4*)lo;
    }
}

// ============================ split-K combines ============================
__global__ void comb9_k(const float* __restrict__ P, const float* __restrict__ ci2,
                        __half* __restrict__ Xcat) {
    int c = threadIdx.x;
    int r = blockIdx.x;
    int z = blockIdx.y;
    size_t pi = (size_t)(z * 2) * N * 128 + (size_t)r * 128 + c;
    float v = P[pi] + P[pi + (size_t)N * 128];
    v = fmaxf(v * ci2[z * N + r], 0.f);
    Xcat[(size_t)r * 256 + z * 128 + c] = __float2half_rn(v);
}

__global__ void comb11_k(const float* __restrict__ P, const __half* __restrict__ Xcw,
                         const float* __restrict__ cis, float* __restrict__ Xor) {
    int c = blockIdx.y * 128 + threadIdx.x;
    int r = blockIdx.x;
    size_t i = (size_t)r * 384 + c;
    float s = 0.f;
    #pragma unroll
    for (int sp = 0; sp < 4; sp++) s += P[(size_t)sp * N * 384 + i];
    s -= __half2float(Xcw[i]);
    Xor[i] = s * cis[r];
}

// ============================ small kernels ============================
__global__ void softmax_init_k(const float* __restrict__ w0a, const float* __restrict__ w0b,
                               const float* __restrict__ w1a, float* __restrict__ sw,
                               float* __restrict__ out) {
    int r = threadIdx.x;
    if (r < 3 * C) {
        int t = r >> 1, c = r & 1;
        const float* src = (t == 0) ? w0a : (t == 1) ? w0b : w1a;
        src += c * E;
        float v[E]; float m = -1e30f;
        #pragma unroll
        for (int e = 0; e < E; e++) { v[e] = src[e]; m = fmaxf(m, v[e]); }
        float s = 0.f;
        #pragma unroll
        for (int e = 0; e < E; e++) { v[e] = expf(v[e] - m); s += v[e]; }
        #pragma unroll
        for (int e = 0; e < E; e++) {
            float q = v[e] / s;
            sw[t * (C * E) + c * E + e] = q;
            out[1 + NT * NUM_CLASS + t * (C * E) + c * E + e] = q;
        }
    }
}

__global__ void gtconv_k(const float* __restrict__ A, const float* __restrict__ sw,
                         __half* __restrict__ pa, __half* __restrict__ pb,
                         __half* __restrict__ pa1) {
    size_t t = (size_t)blockIdx.x * blockDim.x + threadIdx.x;
    if (t * 4 >= NN) return;
    float v[20];
    const float4* Ap = (const float4*)(A + t * 20);
    #pragma unroll
    for (int q = 0; q < 5; q++) {
        float4 f = Ap[q];
        v[q * 4 + 0] = f.x; v[q * 4 + 1] = f.y; v[q * 4 + 2] = f.z; v[q * 4 + 3] = f.w;
    }
    #pragma unroll
    for (int c = 0; c < C; c++) {
        __half ha[4], hb[4], h1[4];
        #pragma unroll
        for (int g = 0; g < 4; g++) {
            float sa = 0.f, sb = 0.f, s1 = 0.f;
            #pragma unroll
            for (int e = 0; e < E; e++) {
                float av = v[g * 5 + e];
                sa = fmaf(sw[c * E + e], av, sa);
                sb = fmaf(sw[C * E + c * E + e], av, sb);
                s1 = fmaf(sw[2 * C * E + c * E + e], av, s1);
            }
            ha[g] = __float2half_rn(sa);
            hb[g] = __float2half_rn(sb);
            h1[g] = __float2half_rn(s1);
        }
        *(uint2*)(pa + c * NN + t * 4) = *(uint2*)ha;
        *(uint2*)(pb + c * NN + t * 4) = *(uint2*)hb;
        *(uint2*)(pa1 + c * NN + t * 4) = *(uint2*)h1;
    }
}

__global__ void scale_a1_k(__half* __restrict__ a1, const float* __restrict__ cinv1) {
    int c8 = threadIdx.x * 8;
    int row = blockIdx.y, z = blockIdx.z;
    size_t i = (size_t)z * NN + (size_t)row * N + c8;
    float sc = cinv1[z * N + row];
    uint4 raw = *(uint4*)(a1 + i);
    __half2* h = (__half2*)&raw;
    #pragma unroll
    for (int q = 0; q < 4; q++) {
        float2 f = __half22float2(h[q]);
        h[q] = __floats2half2_rn(f.x * sc, f.y * sc);
    }
    *(uint4*)(a1 + i) = raw;
}

__global__ void colsum_part_h(const __half* __restrict__ H, float* __restrict__ part, size_t sH) {
    int c8 = threadIdx.x * 8;
    const __half* p = H + (size_t)blockIdx.z * sH + (size_t)blockIdx.y * 32 * N + c8;
    float s[8] = {};
    #pragma unroll 4
    for (int i = 0; i < 32; i++) {
        uint4 raw = *(const uint4*)(p + (size_t)i * N);
        const __half2* h = (const __half2*)&raw;
        #pragma unroll
        for (int q = 0; q < 4; q++) {
            float2 f = __half22float2(h[q]);
            s[q * 2] += f.x; s[q * 2 + 1] += f.y;
        }
    }
    float* dst = part + ((size_t)blockIdx.z * 64 + blockIdx.y) * N + c8;
    *(float4*)dst = make_float4(s[0], s[1], s[2], s[3]);
    *(float4*)(dst + 4) = make_float4(s[4], s[5], s[6], s[7]);
}

__global__ void cinv_fin_k(const float* __restrict__ part, float* __restrict__ cinv) {
    int col = blockIdx.x * 256 + threadIdx.x;
    int z = blockIdx.z;
    float s = 0.f;
    #pragma unroll
    for (int r = 0; r < 64; r++) s += part[((size_t)z * 64 + r) * N + col];
    cinv[z * N + col] = (s == 0.f) ? 0.f : 1.f / s;
}

__global__ void fin2_k(const float* __restrict__ part, float* __restrict__ cinv2,
                       float* __restrict__ cinvs) {
    int col = blockIdx.x * 256 + threadIdx.x;
    float sz[2];
    #pragma unroll
    for (int z = 0; z < 2; z++) {
        float s = 0.f;
        #pragma unroll
        for (int r = 0; r < 64; r++) s += part[((size_t)z * 64 + r) * N + col];
        sz[z] = s;
        cinv2[z * N + col] = (s == 0.f) ? 0.f : 1.f / s;
    }
    float d = sz[0] + sz[1] - 1.f;
    cinvs[col] = (d == 0.f) ? 0.f : 1.f / d;
}

__global__ void y_k(const float* __restrict__ Xo, const float* __restrict__ lw,
                    const float* __restrict__ lb, const int* __restrict__ txp,
                    float* __restrict__ outy) {
    int id = blockIdx.x * blockDim.x + threadIdx.x;
    if (id >= NT * NUM_CLASS) return;
    int t = id / NUM_CLASS, k = id % NUM_CLASS;
    const float* xr = Xo + (size_t)txp[t] * 384;
    const float* wr = lw + (size_t)k * W_OUT;
    float s = 0.f;
    #pragma unroll 4
    for (int d = 0; d < W_OUT; d++) s = fmaf(xr[d], wr[d], s);
    outy[id] = s + lb[k];
}

__global__ void lossC_k(const float* __restrict__ y, const int* __restrict__ tgt,
                        float* __restrict__ part) {
    __shared__ float red[256];
    int t = blockIdx.x * 256 + threadIdx.x;
    float yv[NUM_CLASS];
    float m = -1e30f;
    #pragma unroll
    for (int k = 0; k < NUM_CLASS; k++) { yv[k] = y[t * NUM_CLASS + k]; m = fmaxf(m, yv[k]); }
    float se = 0.f;
    #pragma unroll
    for (int k = 0; k < NUM_CLASS; k++) se += expf(yv[k] - m);
    float lse = m + logf(se);
    red[threadIdx.x] = yv[tgt[t]] - lse;
    __syncthreads();
    for (int s = 128; s > 0; s >>= 1) {
        if (threadIdx.x < s) red[threadIdx.x] += red[threadIdx.x + s];
        __syncthreads();
    }
    if (threadIdx.x == 0) part[blockIdx.x] = red[0];
}

__global__ void lossR_k(const float* __restrict__ XORb, const float* __restrict__ X,
                        float* __restrict__ part) {
    __shared__ float red[256];
    const size_t total = (size_t)N * W_IN;
    size_t tid = (size_t)blockIdx.x * 256 + threadIdx.x;
    size_t stride = (size_t)gridDim.x * 256;
    float acc = 0.f;
    for (size_t i = tid; i < total; i += stride) {
        size_t row = i >> 8, col = i & 255;
        float x = XORb[row * 384 + 128 + col];
        if (x > 1.f || x < 0.f) x = 1.f / (1.f + expf(-x));
        float p = fminf(fmaxf(x, 1e-7f), 1.f - 1e-7f);
        float t = X[i];
        acc += t * logf(p) + (1.f - t) * log1pf(-p);
    }
    red[threadIdx.x] = acc;
    __syncthreads();
    for (int s = 128; s > 0; s >>= 1) {
        if (threadIdx.x < s) red[threadIdx.x] += red[threadIdx.x + s];
        __syncthreads();
    }
    if (threadIdx.x == 0) part[blockIdx.x] = red[0];
}

__global__ void final_k(const float* __restrict__ partR, const float* __restrict__ partC,
                        float* __restrict__ out) {
    __shared__ float red[256];
    red[threadIdx.x] = partR[threadIdx.x] + partR[threadIdx.x + 256];
    __syncthreads();
    for (int s = 128; s > 0; s >>= 1) {
        if (threadIdx.x < s) red[threadIdx.x] += red[threadIdx.x + s];
        __syncthreads();
    }
    if (threadIdx.x == 0) {
        float lossR = -red[0] / (float)((size_t)N * W_IN);
        float sC = partC[0] + partC[1] + partC[2] + partC[3];
        float lossC = -sC / (float)NT;
        out[0] = lossC + lossR;
        out[1 + NT * NUM_CLASS + 3 * C * E] = lossR;
    }
}

// ============================ host side ============================
constexpr int SMEM_BIG = (128 * 72 + 64 * 136) * 2 * 3;       // 107520
constexpr int SMEM_TA  = (64 * 136 + 64 * 136) * 2 * 3;       // 104448
constexpr int SMEM_SPA = (2 * 128 * 72 + 2 * 64 * 136) * 2 * 3;  // 215040
constexpr int SMEM_SPN = (128 * 72 + 2 * 64 * 136) * 2 * 3;      // 159744

extern "C" void kernel_launch(void* const* d_in, const int* in_sizes, int n_in,
                              void* d_out, int out_size) {
    __half* Hh = nullptr;
    float* S = nullptr;
    cudaGetSymbolAddress((void**)&Hh, g_h);
    cudaGetSymbolAddress((void**)&S, g_f);

    const float* A   = (const float*)d_in[0];
    const float* X   = (const float*)d_in[1];
    const float* W   = (const float*)d_in[2];
    const float* W1  = (const float*)d_in[3];
    const float* W2  = (const float*)d_in[4];
    const float* lw  = (const float*)d_in[5];
    const float* lb  = (const float*)d_in[6];
    const float* w0a = (const float*)d_in[7];
    const float* w0b = (const float*)d_in[8];
    const float* w1a = (const float*)d_in[9];
    const int* txp   = (const int*)d_in[10];
    const int* tgt   = (const int*)d_in[11];
    float* out = (float*)d_out;

    cudaFuncSetAttribute((const void*)hgemm_big,
                         cudaFuncAttributeMaxDynamicSharedMemorySize, SMEM_BIG);
    cudaFuncSetAttribute((const void*)hgemm_ta<false>,
                         cudaFuncAttributeMaxDynamicSharedMemorySize, SMEM_TA);
    cudaFuncSetAttribute((const void*)hgemm_ta<true>,
                         cudaFuncAttributeMaxDynamicSharedMemorySize, SMEM_TA);
    cudaFuncSetAttribute((const void*)hgemm_sp<true>,
                         cudaFuncAttributeMaxDynamicSharedMemorySize, SMEM_SPA);
    cudaFuncSetAttribute((const void*)hgemm_sp<false>,
                         cudaFuncAttributeMaxDynamicSharedMemorySize, SMEM_SPN);

    // 1. softmax weights + Ws outputs; operand hi/lo splits
    softmax_init_k<<<1, 32>>>(w0a, w0b, w1a, S + FO_SW, out);
    split_all_k<<<320, 256>>>(X, W, W1, W2,
        Hh + HO_XHI, Hh + HO_XLO, Hh + HO_WHI, Hh + HO_WLO, Hh + HO_WFHI, Hh + HO_WFLO);
    // 2. a, b, a1 (fp16)
    gtconv_k<<<(unsigned)(NN / 4 / 256), 256>>>(A, S + FO_SW, Hh + HO_A, Hh + HO_B, Hh + HO_A1);
    // 3. H = a @ b, diag->0
    hgemm_big<<<dim3(16, 16, 2), 128, SMEM_BIG>>>(Hh + HO_A, Hh + HO_B, Hh + HO_H, 2);
    // 4. cinv1 = 1/colsum(H)
    colsum_part_h<<<dim3(1, 64, 2), 256>>>(Hh + HO_H, S + FO_COLP, NN);
    cinv_fin_k<<<dim3(8, 1, 2), 256>>>(S + FO_COLP, S + FO_CI1);
    // 5. a1 <- diag(cinv1) @ a1  (in place)
    scale_a1_k<<<dim3(1, N, 2), 256>>>(Hh + HO_A1, S + FO_CI1);
    // 6. H2 = H @ a1n, diag->1
    hgemm_big<<<dim3(16, 16, 2), 128, SMEM_BIG>>>(Hh + HO_H, Hh + HO_A1, Hh + HO_H2, 4);
    // 7. cinv2, cinvs from H2 colsums
    colsum_part_h<<<dim3(1, 64, 2), 256>>>(Hh + HO_H2, S + FO_COLP, NN);
    fin2_k<<<8, 256>>>(S + FO_COLP, S + FO_CI2, S + FO_CIS);
    // 8. XW = X @ W  (split-fp16 tensor, f32-accurate)
    hgemm_sp<true><<<dim3(1, 16), 256, SMEM_SPA>>>(
        Hh + HO_XHI, Hh + HO_XLO, Hh + HO_WHI, Hh + HO_WLO, Hh + HO_XW, 256, 256, 128, 128);
    // 9. P[z*2+s] = (H2[z]^T @ XW) k-split partials; combine -> Xcat
    hgemm_ta<false><<<dim3(1, 16, 4), 256, SMEM_TA>>>(
        Hh + HO_H2, Hh + HO_XW, N, N, 128, NN, 2, S + FO_P, 128, (size_t)N * 128);
    comb9_k<<<dim3(N, 2), 128>>>(S + FO_P, S + FO_CI2, Hh + HO_XCAT);
    // 10. Xcw = Xcat @ [W1|W2]  (split-fp16 tensor, one launch)
    hgemm_sp<false><<<dim3(3, 16), 256, SMEM_SPN>>>(
        Hh + HO_XCAT, nullptr, Hh + HO_WFHI, Hh + HO_WFLO, Hh + HO_XCW, 256, 256, 384, 384);
    // 11. P[s] = partial sums of (sum_z H2[z]^T @ Xcw); combine -> Xor (f32)
    hgemm_ta<true><<<dim3(3, 16, 4), 256, SMEM_TA>>>(
        Hh + HO_H2, Hh + HO_XCW, N, N, 384, NN, 4, S + FO_P, 384, (size_t)N * 384);
    comb11_k<<<dim3(N, 3), 128>>>(S + FO_P, Hh + HO_XCW, S + FO_CIS, S + FO_XOR);
    // 12. y, losses, final
    y_k<<<(NT * NUM_CLASS) / 256, 256>>>(S + FO_XOR, lw, lb, txp, out + 1);
    lossC_k<<<NT / 256, 256>>>(out + 1, tgt, S + FO_PC);
    lossR_k<<<512, 256>>>(S + FO_XOR, X, S + FO_PR);
    final_k<<<1, 256>>>(S + FO_PR, S + FO_PC, out);
}

// round 14
// speedup vs baseline: 1.2402x; 1.1293x over previous
#include <cuda_runtime.h>
#include <cuda_fp16.h>
#include <math.h>
#include <stdint.h>

constexpr int N = 2048, E = 5, C = 2, W_IN = 256, W_OUT = 128, NUM_CLASS = 8, NT = 1024;
constexpr size_t NN = (size_t)N * (size_t)N;

// ---------------- half scratch ----------------
constexpr size_t HO_A    = 0;            // a [C,N,N]
constexpr size_t HO_B    = 2 * NN;       // b [C,N,N]
constexpr size_t HO_A1   = 4 * NN;       // a1 raw fp16
constexpr size_t HO_H    = 6 * NN;       // H diag->0
constexpr size_t HO_XW   = 8 * NN;                       // [N,128]
constexpr size_t HO_XCAT = HO_XW   + (size_t)N * 128;    // [N,256]
constexpr size_t HO_XCW  = HO_XCAT + (size_t)N * 256;    // [N,384]
constexpr size_t HO_T1   = HO_XCW  + (size_t)N * 384;    // [2][N][128]
constexpr size_t HO_T2   = HO_T1   + (size_t)2 * N * 128; // [2][N][384]
constexpr size_t HO_XHI  = HO_T2   + (size_t)2 * N * 384;
constexpr size_t HO_XLO  = HO_XHI  + (size_t)N * 256;
constexpr size_t HO_WHI  = HO_XLO  + (size_t)N * 256;
constexpr size_t HO_WLO  = HO_WHI  + (size_t)256 * 128;
constexpr size_t HO_WFHI = HO_WLO  + (size_t)256 * 128;
constexpr size_t HO_WFLO = HO_WFHI + (size_t)256 * 384;
constexpr size_t H_TOTAL = HO_WFLO + (size_t)256 * 384;

// ---------------- float scratch ----------------
constexpr size_t FO_XOR  = 0;                             // [N,384]
constexpr size_t FO_CI1  = FO_XOR  + (size_t)N * 384;     // [2,N]
constexpr size_t FO_CI2  = FO_CI1  + (size_t)2 * N;       // [2,N]
constexpr size_t FO_CIS  = FO_CI2  + (size_t)2 * N;       // [N]
constexpr size_t FO_DG2  = FO_CIS  + N;                   // [2,N]
constexpr size_t FO_DG2S = FO_DG2  + (size_t)2 * N;       // [N]
constexpr size_t FO_COLP = FO_DG2S + N;                   // [2,64,N]
constexpr size_t FO_DGP  = FO_COLP + (size_t)2 * 64 * N;  // [2,8,N]
constexpr size_t FO_SW   = FO_DGP  + (size_t)2 * 8 * N;   // 32
constexpr size_t FO_PR   = FO_SW + 32;                    // 512
constexpr size_t FO_PC   = FO_PR + 512;                   // 16
constexpr size_t FO_P    = FO_PC + 16;                    // [4][N][384]
constexpr size_t F_TOTAL = FO_P + (size_t)4 * N * 384;

__device__ __align__(1024) __half g_h[H_TOTAL];
__device__ __align__(1024) float  g_f[F_TOTAL];

// ============================ helpers ============================
__device__ __forceinline__ uint32_t smem_u32(const void* p) {
    uint32_t a;
    asm("{ .reg .u64 t; cvta.to.shared.u64 t, %1; cvt.u32.u64 %0, t; }" : "=r"(a) : "l"(p));
    return a;
}
__device__ __forceinline__ void cpa16(uint32_t saddr, const void* g) {
    asm volatile("cp.async.cg.shared.global [%0], [%1], 16;" :: "r"(saddr), "l"(g));
}
#define CP_COMMIT() asm volatile("cp.async.commit_group;" ::: "memory")

__device__ __forceinline__ void ldsm_x4(uint32_t* r, uint32_t a) {
    asm volatile("ldmatrix.sync.aligned.m8n8.x4.shared.b16 {%0,%1,%2,%3}, [%4];"
        : "=r"(r[0]), "=r"(r[1]), "=r"(r[2]), "=r"(r[3]) : "r"(a));
}
__device__ __forceinline__ void ldsm_x4t(uint32_t* r, uint32_t a) {
    asm volatile("ldmatrix.sync.aligned.m8n8.x4.trans.shared.b16 {%0,%1,%2,%3}, [%4];"
        : "=r"(r[0]), "=r"(r[1]), "=r"(r[2]), "=r"(r[3]) : "r"(a));
}
__device__ __forceinline__ void mma16816(float* d, const uint32_t* a, const uint32_t* b) {
    asm volatile(
        "mma.sync.aligned.m16n8k16.row.col.f32.f16.f16.f32 "
        "{%0,%1,%2,%3}, {%4,%5,%6,%7}, {%8,%9}, {%0,%1,%2,%3};"
        : "+f"(d[0]), "+f"(d[1]), "+f"(d[2]), "+f"(d[3])
        : "r"(a[0]), "r"(a[1]), "r"(a[2]), "r"(a[3]), "r"(b[0]), "r"(b[1]));
}

// ============================ big square GEMM (used ONCE: H = a@b) ============================
__global__ void __launch_bounds__(128, 2)
hgemm_big(const __half* __restrict__ A, const __half* __restrict__ B, __half* __restrict__ Cout,
          int flags) {
    extern __shared__ __half sm[];
    constexpr int A_H = 128 * 72;
    constexpr int B_H = 64 * 136;
    constexpr int STG = A_H + B_H;

    const int tid = threadIdx.x, lane = tid & 31, wid = tid >> 5;
    const int wm = wid >> 1, wn = wid & 1;
    const int m0 = blockIdx.y * 128, n0 = blockIdx.x * 128;
    const size_t zoff = (size_t)blockIdx.z * NN;
    A += zoff; B += zoff; Cout += zoff;
    const uint32_t sb = smem_u32(sm);

    float acc[4][8][4] = {};

    auto fill = [&](int s, int k0) {
        uint32_t sa = sb + (uint32_t)s * STG * 2;
        #pragma unroll
        for (int e = 0; e < 8; e++) {
            int c = tid + e * 128;
            int m = c >> 3, ch = c & 7;
            cpa16(sa + (m * 72 + ch * 8) * 2, A + (size_t)(m0 + m) * N + k0 + ch * 8);
        }
        uint32_t sbb = sa + A_H * 2;
        #pragma unroll
        for (int e = 0; e < 8; e++) {
            int c = tid + e * 128;
            int kk = c >> 4, ch = c & 15;
            cpa16(sbb + (kk * 136 + ch * 8) * 2, B + (size_t)(k0 + kk) * N + n0 + ch * 8);
        }
        CP_COMMIT();
    };

    constexpr int NIT = N / 64;
    fill(0, 0);
    fill(1, 64);

    for (int j = 0; j < NIT; j++) {
        if (j + 1 < NIT) asm volatile("cp.async.wait_group 1;" ::: "memory");
        else             asm volatile("cp.async.wait_group 0;" ::: "memory");
        __syncthreads();
        if (j + 2 < NIT) fill((j + 2) % 3, (j + 2) * 64);
        uint32_t sa = sb + (uint32_t)(j % 3) * STG * 2;
        uint32_t sbs = sa + A_H * 2;
        #pragma unroll
        for (int ks = 0; ks < 4; ks++) {
            uint32_t af[4][4], bf[4][4];
            #pragma unroll
            for (int mt = 0; mt < 4; mt++) {
                int row = wm * 64 + mt * 16 + (lane & 7) + ((lane >> 3) & 1) * 8;
                int col = ks * 16 + (lane >> 4) * 8;
                ldsm_x4(af[mt], sa + (row * 72 + col) * 2);
            }
            #pragma unroll
            for (int np = 0; np < 4; np++) {
                int kr = ks * 16 + (lane & 7) + ((lane >> 3) & 1) * 8;
                int col = wn * 64 + np * 16 + (lane >> 4) * 8;
                ldsm_x4t(bf[np], sbs + (kr * 136 + col) * 2);
            }
            #pragma unroll
            for (int mt = 0; mt < 4; mt++)
                #pragma unroll
                for (int nt = 0; nt < 8; nt++)
                    mma16816(acc[mt][nt], af[mt], &bf[nt >> 1][(nt & 1) * 2]);
        }
    }

    #pragma unroll
    for (int mt = 0; mt < 4; mt++) {
        #pragma unroll
        for (int hf = 0; hf < 2; hf++) {
            int r = m0 + wm * 64 + mt * 16 + (lane >> 2) + hf * 8;
            #pragma unroll
            for (int nt = 0; nt < 8; nt++) {
                int cc = n0 + wn * 64 + nt * 8 + (lane & 3) * 2;
                float v0 = acc[mt][nt][hf * 2 + 0];
                float v1 = acc[mt][nt][hf * 2 + 1];
                if (flags & 2) { if (r == cc) v0 = 0.f; if (r == cc + 1) v1 = 0.f; }
                if (flags & 4) { if (r == cc) v0 = 1.f; if (r == cc + 1) v1 = 1.f; }
                *(__half2*)(Cout + (size_t)r * N + cc) = __floats2half2_rn(v0, v1);
            }
        }
    }
}

// ============================ TRANSA fp16 GEMM (split-K f32 partials) ============================
// partial[(z,split)] = Aop^T slice @ B;  Aop = A[k][m].  SUMZ: K-space spans 2 z-planes (A and B).
template <bool SUMZ>
__global__ void __launch_bounds__(256, 2)
hgemm_ta(const __half* __restrict__ A, const __half* __restrict__ B,
         int K, int lda, int ldb, size_t szA, size_t szB, int nsplit,
         float* __restrict__ pbuf, int ldp, size_t pstride) {
    extern __shared__ __half sm[];
    constexpr int A_H = 64 * 136;
    constexpr int B_H = 64 * 136;
    constexpr int STG = A_H + B_H;

    const int tid = threadIdx.x, lane = tid & 31, wid = tid >> 5;
    const int wm = wid >> 2, wn = wid & 3;
    const int m0 = blockIdx.y * 128, n0 = blockIdx.x * 128;
    const int z = blockIdx.z / nsplit;
    const int split = blockIdx.z % nsplit;
    if (!SUMZ) { A += (size_t)z * szA; B += (size_t)z * szB; }
    const uint32_t sb = smem_u32(sm);

    float acc[4][4][4] = {};

    const int total_slabs = (SUMZ ? 2 * K : K) / 64;
    const int nit = total_slabs / nsplit;
    const int start = split * nit;

    auto fillA = [&](int s, int g) {
        int zz = SUMZ ? (g * 64) / K : 0;
        int k0 = SUMZ ? (g * 64) % K : g * 64;
        uint32_t sa = sb + (uint32_t)s * STG * 2;
        const __half* Ap = SUMZ ? A + (size_t)zz * szA : A;
        const __half* Bp = SUMZ ? B + (size_t)zz * szB : B;
        #pragma unroll
        for (int e = 0; e < 4; e++) {
            int c = tid + e * 256;
            int kk = c >> 4, ch = c & 15;
            cpa16(sa + (kk * 136 + ch * 8) * 2, Ap + (size_t)(k0 + kk) * lda + m0 + ch * 8);
        }
        uint32_t sbb = sa + A_H * 2;
        #pragma unroll
        for (int e = 0; e < 4; e++) {
            int c = tid + e * 256;
            int kk = c >> 4, ch = c & 15;
            cpa16(sbb + (kk * 136 + ch * 8) * 2, Bp + (size_t)(k0 + kk) * ldb + n0 + ch * 8);
        }
        CP_COMMIT();
    };

    fillA(0, start);
    fillA(1, start + 1);

    for (int j = 0; j < nit; j++) {
        if (j + 1 < nit) asm volatile("cp.async.wait_group 1;" ::: "memory");
        else             asm volatile("cp.async.wait_group 0;" ::: "memory");
        __syncthreads();
        if (j + 2 < nit) fillA((j + 2) % 3, start + j + 2);
        uint32_t sa = sb + (uint32_t)(j % 3) * STG * 2;
        uint32_t sbs = sa + A_H * 2;
        #pragma unroll
        for (int ks = 0; ks < 4; ks++) {
            uint32_t af[4][4], bf[2][4];
            #pragma unroll
            for (int mt = 0; mt < 4; mt++) {
                int kr = ks * 16 + (lane & 7) + (lane >> 4) * 8;
                int mc = wm * 64 + mt * 16 + ((lane >> 3) & 1) * 8;
                ldsm_x4t(af[mt], sa + (kr * 136 + mc) * 2);
            }
            #pragma unroll
            for (int np = 0; np < 2; np++) {
                int kr = ks * 16 + (lane & 7) + ((lane >> 3) & 1) * 8;
                int col = wn * 32 + np * 16 + (lane >> 4) * 8;
                ldsm_x4t(bf[np], sbs + (kr * 136 + col) * 2);
            }
            #pragma unroll
            for (int mt = 0; mt < 4; mt++)
                #pragma unroll
                for (int nt = 0; nt < 4; nt++)
                    mma16816(acc[mt][nt], af[mt], &bf[nt >> 1][(nt & 1) * 2]);
        }
    }

    float* P = pbuf + (size_t)blockIdx.z * pstride;
    #pragma unroll
    for (int mt = 0; mt < 4; mt++)
        #pragma unroll
        for (int hf = 0; hf < 2; hf++) {
            int r = m0 + wm * 64 + mt * 16 + (lane >> 2) + hf * 8;
            #pragma unroll
            for (int nt = 0; nt < 4; nt++) {
                int cc = n0 + wn * 32 + nt * 8 + (lane & 3) * 2;
                *(float2*)(P + (size_t)r * ldp + cc) =
                    make_float2(acc[mt][nt][hf * 2], acc[mt][nt][hf * 2 + 1]);
            }
        }
}

// ============================ split-fp16 small GEMM (f32-accurate) ============================
template <bool ASPLIT>
__global__ void __launch_bounds__(256)
hgemm_sp(const __half* __restrict__ Ah, const __half* __restrict__ Al,
         const __half* __restrict__ Bh, const __half* __restrict__ Bl,
         __half* __restrict__ Cout, int K, int lda, int ldb, int ldc) {
    extern __shared__ __half sm[];
    constexpr int A_SZ = 128 * 72;
    constexpr int B_SZ = 64 * 136;
    constexpr int A_TOT = ASPLIT ? 2 * A_SZ : A_SZ;
    constexpr int STG = A_TOT + 2 * B_SZ;

    const int tid = threadIdx.x, lane = tid & 31, wid = tid >> 5;
    const int wm = wid >> 2, wn = wid & 3;
    const int m0 = blockIdx.y * 128, n0 = blockIdx.x * 128;
    const uint32_t sb = smem_u32(sm);

    float acc[4][4][4] = {};

    auto fill = [&](int s, int k0) {
        uint32_t sa = sb + (uint32_t)s * STG * 2;
        #pragma unroll
        for (int e = 0; e < 4; e++) {
            int c = tid + e * 256;
            int m = c >> 3, ch = c & 7;
            cpa16(sa + (m * 72 + ch * 8) * 2, Ah + (size_t)(m0 + m) * lda + k0 + ch * 8);
        }
        if (ASPLIT) {
            uint32_t sal = sa + A_SZ * 2;
            #pragma unroll
            for (int e = 0; e < 4; e++) {
                int c = tid + e * 256;
                int m = c >> 3, ch = c & 7;
                cpa16(sal + (m * 72 + ch * 8) * 2, Al + (size_t)(m0 + m) * lda + k0 + ch * 8);
            }
        }
        uint32_t sbh = sa + A_TOT * 2;
        uint32_t sbl = sbh + B_SZ * 2;
        #pragma unroll
        for (int e = 0; e < 4; e++) {
            int c = tid + e * 256;
            int kk = c >> 4, ch = c & 15;
            cpa16(sbh + (kk * 136 + ch * 8) * 2, Bh + (size_t)(k0 + kk) * ldb + n0 + ch * 8);
            cpa16(sbl + (kk * 136 + ch * 8) * 2, Bl + (size_t)(k0 + kk) * ldb + n0 + ch * 8);
        }
        CP_COMMIT();
    };

    const int nit = K / 64;
    fill(0, 0);
    if (nit > 1) fill(1, 64);

    for (int j = 0; j < nit; j++) {
        if (j + 1 < nit) asm volatile("cp.async.wait_group 1;" ::: "memory");
        else             asm volatile("cp.async.wait_group 0;" ::: "memory");
        __syncthreads();
        if (j + 2 < nit) fill((j + 2) % 3, (j + 2) * 64);
        uint32_t sa = sb + (uint32_t)(j % 3) * STG * 2;
        uint32_t sbh = sa + A_TOT * 2;
        uint32_t sbl = sbh + B_SZ * 2;
        #pragma unroll
        for (int ks = 0; ks < 4; ks++) {
            uint32_t afh[4][4], afl[4][4], bfh[2][4], bfl[2][4];
            #pragma unroll
            for (int mt = 0; mt < 4; mt++) {
                int row = wm * 64 + mt * 16 + (lane & 7) + ((lane >> 3) & 1) * 8;
                int col = ks * 16 + (lane >> 4) * 8;
                ldsm_x4(afh[mt], sa + (row * 72 + col) * 2);
                if (ASPLIT) ldsm_x4(afl[mt], sa + (A_SZ + row * 72 + col) * 2);
            }
            #pragma unroll
            for (int np = 0; np < 2; np++) {
                int kr = ks * 16 + (lane & 7) + ((lane >> 3) & 1) * 8;
                int col = wn * 32 + np * 16 + (lane >> 4) * 8;
                ldsm_x4t(bfh[np], sbh + (kr * 136 + col) * 2);
                ldsm_x4t(bfl[np], sbl + (kr * 136 + col) * 2);
            }
            #pragma unroll
            for (int mt = 0; mt < 4; mt++)
                #pragma unroll
                for (int nt = 0; nt < 4; nt++) {
                    mma16816(acc[mt][nt], afh[mt], &bfh[nt >> 1][(nt & 1) * 2]);
                    mma16816(acc[mt][nt], afh[mt], &bfl[nt >> 1][(nt & 1) * 2]);
                    if (ASPLIT)
                        mma16816(acc[mt][nt], afl[mt], &bfh[nt >> 1][(nt & 1) * 2]);
                }
        }
    }

    #pragma unroll
    for (int mt = 0; mt < 4; mt++)
        #pragma unroll
        for (int hf = 0; hf < 2; hf++) {
            int r = m0 + wm * 64 + mt * 16 + (lane >> 2) + hf * 8;
            #pragma unroll
            for (int nt = 0; nt < 4; nt++) {
                int cc = n0 + wn * 32 + nt * 8 + (lane & 3) * 2;
                *(__half2*)(Cout + (size_t)r * ldc + cc) =
                    __floats2half2_rn(acc[mt][nt][hf * 2], acc[mt][nt][hf * 2 + 1]);
            }
        }
}

// ============================ diag(H2) via tiled transpose-mult-reduce ============================
// dgp[z][kb][j] = sum_{k in kb-chunk} H[z][j][k] * cinv1[z][k] * a1[z][k][j]
__global__ void __launch_bounds__(256)
dg2_k(const __half* __restrict__ H, const __half* __restrict__ a1,
      const float* __restrict__ cv1, float* __restrict__ dgp) {
    __shared__ float Htf[64][65];
    __shared__ float Atf[64][65];
    __shared__ float cvs[256];
    __shared__ float red[4][64];
    const int jb = blockIdx.x * 64, kc = blockIdx.y * 256, z = blockIdx.z;
    const __half* Hp = H + (size_t)z * NN;
    const __half* Ap = a1 + (size_t)z * NN;
    const int tid = threadIdx.x;
    cvs[tid] = cv1[z * N + kc + tid];
    const int j = tid & 63, g = tid >> 6;
    float partial = 0.f;
    for (int ks = 0; ks < 4; ks++) {
        int k0 = kc + ks * 64;
        __syncthreads();
        #pragma unroll
        for (int e = 0; e < 2; e++) {
            int idx = tid + e * 256;
            int r = idx >> 3, c8 = (idx & 7) * 8;
            uint4 raw = *(const uint4*)(Hp + (size_t)(jb + r) * N + k0 + c8);
            const __half* hh = (const __half*)&raw;
            #pragma unroll
            for (int q = 0; q < 8; q++) Htf[r][c8 + q] = __half2float(hh[q]);
        }
        #pragma unroll
        for (int e = 0; e < 2; e++) {
            int idx = tid + e * 256;
            int r = idx >> 3, c8 = (idx & 7) * 8;
            uint4 raw = *(const uint4*)(Ap + (size_t)(k0 + r) * N + jb + c8);
            const __half* hh = (const __half*)&raw;
            #pragma unroll
            for (int q = 0; q < 8; q++) Atf[r][c8 + q] = __half2float(hh[q]);
        }
        __syncthreads();
        #pragma unroll
        for (int ci = 0; ci < 16; ci++) {
            int c = g * 16 + ci;
            partial = fmaf(Htf[j][c] * cvs[ks * 64 + c], Atf[c][j], partial);
        }
    }
    __syncthreads();
    red[g][j] = partial;
    __syncthreads();
    if (g == 0)
        dgp[((size_t)z * 8 + blockIdx.y) * N + jb + j] =
            red[0][j] + red[1][j] + red[2][j] + red[3][j];
}

// ============================ combines / normalizers ============================
// T[z][k][c] = half( cv1[z][k] * (P[z*2] + P[z*2+1])[k][c] )
__global__ void combT_k(const float* __restrict__ P, const float* __restrict__ cv1,
                        __half* __restrict__ T, int width) {
    int c = blockIdx.y * 128 + threadIdx.x;
    int k = blockIdx.x, z = blockIdx.z;
    size_t pi = (size_t)(z * 2) * N * width + (size_t)k * width + c;
    float v = P[pi] + P[pi + (size_t)N * width];
    T[(size_t)z * N * width + (size_t)k * width + c] = __float2half_rn(cv1[z * N + k] * v);
}

// Xcat = relu( ci2 * (P + (1-dg2)*XW) )
__global__ void comb9_k(const float* __restrict__ P, const float* __restrict__ ci2,
                        const float* __restrict__ dg2, const __half* __restrict__ XW,
                        __half* __restrict__ Xcat) {
    int c = threadIdx.x;
    int r = blockIdx.x, z = blockIdx.y;
    size_t pi = (size_t)(z * 2) * N * 128 + (size_t)r * 128 + c;
    float v = P[pi] + P[pi + (size_t)N * 128];
    float xw = __half2float(XW[(size_t)r * 128 + c]);
    v = (v + (1.f - dg2[z * N + r]) * xw) * ci2[z * N + r];
    Xcat[(size_t)r * 256 + z * 128 + c] = __float2half_rn(fmaxf(v, 0.f));
}

// Xor = cis * (sum_s P + (1-dg2s)*Xcw)
__global__ void comb11_k(const float* __restrict__ P, const __half* __restrict__ Xcw,
                         const float* __restrict__ cis, const float* __restrict__ dg2s,
                         float* __restrict__ Xor) {
    int c = blockIdx.y * 128 + threadIdx.x;
    int r = blockIdx.x;
    size_t i = (size_t)r * 384 + c;
    float s = 0.f;
    #pragma unroll
    for (int sp = 0; sp < 4; sp++) s += P[(size_t)sp * N * 384 + i];
    s += (1.f - dg2s[r]) * __half2float(Xcw[i]);
    Xor[i] = s * cis[r];
}

// ============================ small kernels ============================
__global__ void softmax_init_k(const float* __restrict__ w0a, const float* __restrict__ w0b,
                               const float* __restrict__ w1a, float* __restrict__ sw,
                               float* __restrict__ out) {
    int r = threadIdx.x;
    if (r < 3 * C) {
        int t = r >> 1, c = r & 1;
        const float* src = (t == 0) ? w0a : (t == 1) ? w0b : w1a;
        src += c * E;
        float v[E]; float m = -1e30f;
        #pragma unroll
        for (int e = 0; e < E; e++) { v[e] = src[e]; m = fmaxf(m, v[e]); }
        float s = 0.f;
        #pragma unroll
        for (int e = 0; e < E; e++) { v[e] = expf(v[e] - m); s += v[e]; }
        #pragma unroll
        for (int e = 0; e < E; e++) {
            float q = v[e] / s;
            sw[t * (C * E) + c * E + e] = q;
            out[1 + NT * NUM_CLASS + t * (C * E) + c * E + e] = q;
        }
    }
}

__global__ void gtconv_k(const float* __restrict__ A, const float* __restrict__ sw,
                         __half* __restrict__ pa, __half* __restrict__ pb,
                         __half* __restrict__ pa1) {
    size_t t = (size_t)blockIdx.x * blockDim.x + threadIdx.x;
    if (t * 4 >= NN) return;
    float v[20];
    const float4* Ap = (const float4*)(A + t * 20);
    #pragma unroll
    for (int q = 0; q < 5; q++) {
        float4 f = Ap[q];
        v[q * 4 + 0] = f.x; v[q * 4 + 1] = f.y; v[q * 4 + 2] = f.z; v[q * 4 + 3] = f.w;
    }
    #pragma unroll
    for (int c = 0; c < C; c++) {
        __half ha[4], hb[4], h1[4];
        #pragma unroll
        for (int g = 0; g < 4; g++) {
            float sa = 0.f, sb = 0.f, s1 = 0.f;
            #pragma unroll
            for (int e = 0; e < E; e++) {
                float av = v[g * 5 + e];
                sa = fmaf(sw[c * E + e], av, sa);
                sb = fmaf(sw[C * E + c * E + e], av, sb);
                s1 = fmaf(sw[2 * C * E + c * E + e], av, s1);
            }
            ha[g] = __float2half_rn(sa);
            hb[g] = __float2half_rn(sb);
            h1[g] = __float2half_rn(s1);
        }
        *(uint2*)(pa + c * NN + t * 4) = *(uint2*)ha;
        *(uint2*)(pb + c * NN + t * 4) = *(uint2*)hb;
        *(uint2*)(pa1 + c * NN + t * 4) = *(uint2*)h1;
    }
}

__global__ void split_all_k(const float* __restrict__ X, const float* __restrict__ W,
                            const float* __restrict__ W1, const float* __restrict__ W2,
                            __half* __restrict__ Xhi, __half* __restrict__ Xlo,
                            __half* __restrict__ Whi, __half* __restrict__ Wlo,
                            __half* __restrict__ Wfhi, __half* __restrict__ Wflo) {
    int b = blockIdx.x;
    __half hi[8], lo[8];
    if (b < 256) {
        size_t base = (size_t)b * 2048 + threadIdx.x * 8;
        #pragma unroll
        for (int q = 0; q < 8; q++) {
            float x = X[base + q];
            __half h = __float2half_rn(x);
            hi[q] = h;
            lo[q] = __float2half_rn(x - __half2float(h));
        }
        *(uint4*)(Xhi + base) = *(uint4*)hi;
        *(uint4*)(Xlo + base) = *(uint4*)lo;
    } else if (b < 272) {
        size_t base = (size_t)(b - 256) * 2048 + threadIdx.x * 8;
        #pragma unroll
        for (int q = 0; q < 8; q++) {
            float x = W[base + q];
            __half h = __float2half_rn(x);
            hi[q] = h;
            lo[q] = __float2half_rn(x - __half2float(h));
        }
        *(uint4*)(Whi + base) = *(uint4*)hi;
        *(uint4*)(Wlo + base) = *(uint4*)lo;
    } else {
        size_t base = (size_t)(b - 272) * 2048 + threadIdx.x * 8;
        int k = (int)(base / 384), c = (int)(base % 384);
        #pragma unroll
        for (int q = 0; q < 8; q++) {
            int cc = c + q;
            float x = (cc < 128) ? W1[k * 128 + cc] : W2[k * 256 + (cc - 128)];
            __half h = __float2half_rn(x);
            hi[q] = h;
            lo[q] = __float2half_rn(x - __half2float(h));
        }
        *(uint4*)(Wfhi + base) = *(uint4*)hi;
        *(uint4*)(Wflo + base) = *(uint4*)lo;
    }
}

__global__ void colsum_part_h(const __half* __restrict__ H, float* __restrict__ part, size_t sH) {
    int c8 = threadIdx.x * 8;
    const __half* p = H + (size_t)blockIdx.z * sH + (size_t)blockIdx.y * 32 * N + c8;
    float s[8] = {};
    #pragma unroll 4
    for (int i = 0; i < 32; i++) {
        uint4 raw = *(const uint4*)(p + (size_t)i * N);
        const __half2* h = (const __half2*)&raw;
        #pragma unroll
        for (int q = 0; q < 4; q++) {
            float2 f = __half22float2(h[q]);
            s[q * 2] += f.x; s[q * 2 + 1] += f.y;
        }
    }
    float* dst = part + ((size_t)blockIdx.z * 64 + blockIdx.y) * N + c8;
    *(float4*)dst = make_float4(s[0], s[1], s[2], s[3]);
    *(float4*)(dst + 4) = make_float4(s[4], s[5], s[6], s[7]);
}

__global__ void cinv_fin_k(const float* __restrict__ part, float* __restrict__ cinv) {
    int col = blockIdx.x * 256 + threadIdx.x;
    int z = blockIdx.z;
    float s = 0.f;
    #pragma unroll
    for (int r = 0; r < 64; r++) s += part[((size_t)z * 64 + r) * N + col];
    cinv[z * N + col] = (s == 0.f) ? 0.f : 1.f / s;
}

// ci2/cis/dg2s from a1-colsum parts + dg2 partials
__global__ void fin2b_k(const float* __restrict__ parts, const float* __restrict__ dgp,
                        float* __restrict__ ci2, float* __restrict__ cis,
                        float* __restrict__ dg2, float* __restrict__ dg2s) {
    int j = blockIdx.x * 256 + threadIdx.x;
    float tot = 0.f, ds = 0.f;
    #pragma unroll
    for (int z = 0; z < 2; z++) {
        float cs = 0.f;
        #pragma unroll
        for (int r = 0; r < 64; r++) cs += parts[((size_t)z * 64 + r) * N + j];
        float d = 0.f;
        #pragma unroll
        for (int r = 0; r < 8; r++) d += dgp[((size_t)z * 8 + r) * N + j];
        dg2[z * N + j] = d;
        float off = cs - d;
        float den = 1.f + off;
        ci2[z * N + j] = (den == 0.f) ? 0.f : 1.f / den;
        tot += off; ds += d;
    }
    float den = 1.f + tot;
    cis[j] = (den == 0.f) ? 0.f : 1.f / den;
    dg2s[j] = ds;
}

__global__ void y_k(const float* __restrict__ Xo, const float* __restrict__ lw,
                    const float* __restrict__ lb, const int* __restrict__ txp,
                    float* __restrict__ outy) {
    int id = blockIdx.x * blockDim.x + threadIdx.x;
    if (id >= NT * NUM_CLASS) return;
    int t = id / NUM_CLASS, k = id % NUM_CLASS;
    const float* xr = Xo + (size_t)txp[t] * 384;
    const float* wr = lw + (size_t)k * W_OUT;
    float s = 0.f;
    #pragma unroll 4
    for (int d = 0; d < W_OUT; d++) s = fmaf(xr[d], wr[d], s);
    outy[id] = s + lb[k];
}

__global__ void lossC_k(const float* __restrict__ y, const int* __restrict__ tgt,
                        float* __restrict__ part) {
    __shared__ float red[256];
    int t = blockIdx.x * 256 + threadIdx.x;
    float yv[NUM_CLASS];
    float m = -1e30f;
    #pragma unroll
    for (int k = 0; k < NUM_CLASS; k++) { yv[k] = y[t * NUM_CLASS + k]; m = fmaxf(m, yv[k]); }
    float se = 0.f;
    #pragma unroll
    for (int k = 0; k < NUM_CLASS; k++) se += expf(yv[k] - m);
    float lse = m + logf(se);
    red[threadIdx.x] = yv[tgt[t]] - lse;
    __syncthreads();
    for (int s = 128; s > 0; s >>= 1) {
        if (threadIdx.x < s) red[threadIdx.x] += red[threadIdx.x + s];
        __syncthreads();
    }
    if (threadIdx.x == 0) part[blockIdx.x] = red[0];
}

__global__ void lossR_k(const float* __restrict__ XORb, const float* __restrict__ X,
                        float* __restrict__ part) {
    __shared__ float red[256];
    const size_t total = (size_t)N * W_IN;
    size_t tid = (size_t)blockIdx.x * 256 + threadIdx.x;
    size_t stride = (size_t)gridDim.x * 256;
    float acc = 0.f;
    for (size_t i = tid; i < total; i += stride) {
        size_t row = i >> 8, col = i & 255;
        float x = XORb[row * 384 + 128 + col];
        if (x > 1.f || x < 0.f) x = 1.f / (1.f + expf(-x));
        float p = fminf(fmaxf(x, 1e-7f), 1.f - 1e-7f);
        float t = X[i];
        acc += t * logf(p) + (1.f - t) * log1pf(-p);
    }
    red[threadIdx.x] = acc;
    __syncthreads();
    for (int s = 128; s > 0; s >>= 1) {
        if (threadIdx.x < s) red[threadIdx.x] += red[threadIdx.x + s];
        __syncthreads();
    }
    if (threadIdx.x == 0) part[blockIdx.x] = red[0];
}

__global__ void final_k(const float* __restrict__ partR, const float* __restrict__ partC,
                        float* __restrict__ out) {
    __shared__ float red[256];
    red[threadIdx.x] = partR[threadIdx.x] + partR[threadIdx.x + 256];
    __syncthreads();
    for (int s = 128; s > 0; s >>= 1) {
        if (threadIdx.x < s) red[threadIdx.x] += red[threadIdx.x + s];
        __syncthreads();
    }
    if (threadIdx.x == 0) {
        float lossR = -red[0] / (float)((size_t)N * W_IN);
        float sC = partC[0] + partC[1] + partC[2] + partC[3];
        float lossC = -sC / (float)NT;
        out[0] = lossC + lossR;
        out[1 + NT * NUM_CLASS + 3 * C * E] = lossR;
    }
}

// ============================ host side ============================
constexpr int SMEM_BIG = (128 * 72 + 64 * 136) * 2 * 3;
constexpr int SMEM_TA  = (64 * 136 + 64 * 136) * 2 * 3;
constexpr int SMEM_SPA = (2 * 128 * 72 + 2 * 64 * 136) * 2 * 3;
constexpr int SMEM_SPN = (128 * 72 + 2 * 64 * 136) * 2 * 3;

extern "C" void kernel_launch(void* const* d_in, const int* in_sizes, int n_in,
                              void* d_out, int out_size) {
    __half* Hh = nullptr;
    float* S = nullptr;
    cudaGetSymbolAddress((void**)&Hh, g_h);
    cudaGetSymbolAddress((void**)&S, g_f);

    const float* A   = (const float*)d_in[0];
    const float* X   = (const float*)d_in[1];
    const float* W   = (const float*)d_in[2];
    const float* W1  = (const float*)d_in[3];
    const float* W2  = (const float*)d_in[4];
    const float* lw  = (const float*)d_in[5];
    const float* lb  = (const float*)d_in[6];
    const float* w0a = (const float*)d_in[7];
    const float* w0b = (const float*)d_in[8];
    const float* w1a = (const float*)d_in[9];
    const int* txp   = (const int*)d_in[10];
    const int* tgt   = (const int*)d_in[11];
    float* out = (float*)d_out;

    cudaFuncSetAttribute((const void*)hgemm_big,
                         cudaFuncAttributeMaxDynamicSharedMemorySize, SMEM_BIG);
    cudaFuncSetAttribute((const void*)hgemm_ta<false>,
                         cudaFuncAttributeMaxDynamicSharedMemorySize, SMEM_TA);
    cudaFuncSetAttribute((const void*)hgemm_ta<true>,
                         cudaFuncAttributeMaxDynamicSharedMemorySize, SMEM_TA);
    cudaFuncSetAttribute((const void*)hgemm_sp<true>,
                         cudaFuncAttributeMaxDynamicSharedMemorySize, SMEM_SPA);
    cudaFuncSetAttribute((const void*)hgemm_sp<false>,
                         cudaFuncAttributeMaxDynamicSharedMemorySize, SMEM_SPN);

    // 1. softmax weights + Ws outputs; hi/lo operand splits
    softmax_init_k<<<1, 32>>>(w0a, w0b, w1a, S + FO_SW, out);
    split_all_k<<<320, 256>>>(X, W, W1, W2,
        Hh + HO_XHI, Hh + HO_XLO, Hh + HO_WHI, Hh + HO_WLO, Hh + HO_WFHI, Hh + HO_WFLO);
    // 2. a, b, a1 (fp16)
    gtconv_k<<<(unsigned)(NN / 4 / 256), 256>>>(A, S + FO_SW, Hh + HO_A, Hh + HO_B, Hh + HO_A1);
    // 3. H = a @ b, diag->0   (the ONLY N^3 GEMM)
    hgemm_big<<<dim3(16, 16, 2), 128, SMEM_BIG>>>(Hh + HO_A, Hh + HO_B, Hh + HO_H, 2);
    // 4. cinv1 = 1/colsum(H)
    colsum_part_h<<<dim3(1, 64, 2), 256>>>(Hh + HO_H, S + FO_COLP, NN);
    cinv_fin_k<<<dim3(8, 1, 2), 256>>>(S + FO_COLP, S + FO_CI1);
    // 5. dg2 partials = diag(H2) pieces; a1 colsums (= colsum(H2))
    dg2_k<<<dim3(32, 8, 2), 256>>>(Hh + HO_H, Hh + HO_A1, S + FO_CI1, S + FO_DGP);
    colsum_part_h<<<dim3(1, 64, 2), 256>>>(Hh + HO_A1, S + FO_COLP, NN);
    fin2b_k<<<8, 256>>>(S + FO_COLP, S + FO_DGP, S + FO_CI2, S + FO_CIS,
                        S + FO_DG2, S + FO_DG2S);
    // 6. XW = X @ W  (split-fp16, f32-accurate)
    hgemm_sp<true><<<dim3(1, 16), 256, SMEM_SPA>>>(
        Hh + HO_XHI, Hh + HO_XLO, Hh + HO_WHI, Hh + HO_WLO, Hh + HO_XW, 256, 256, 128, 128);
    // 7. T1[z] = cinv1 * (H^T[z] @ XW)
    hgemm_ta<false><<<dim3(1, 16, 4), 256, SMEM_TA>>>(
        Hh + HO_H, Hh + HO_XW, N, N, 128, NN, 0, 2, S + FO_P, 128, (size_t)N * 128);
    combT_k<<<dim3(N, 1, 2), 128>>>(S + FO_P, S + FO_CI1, Hh + HO_T1, 128);
    // 8. P = a1^T[z] @ T1[z]; Xcat = relu(ci2*(P + (1-dg2)*XW))
    hgemm_ta<false><<<dim3(1, 16, 4), 256, SMEM_TA>>>(
        Hh + HO_A1, Hh + HO_T1, N, N, 128, NN, (size_t)N * 128, 2,
        S + FO_P, 128, (size_t)N * 128);
    comb9_k<<<dim3(N, 2), 128>>>(S + FO_P, S + FO_CI2, S + FO_DG2, Hh + HO_XW, Hh + HO_XCAT);
    // 9. Xcw = Xcat @ [W1|W2]  (split-fp16)
    hgemm_sp<false><<<dim3(3, 16), 256, SMEM_SPN>>>(
        Hh + HO_XCAT, nullptr, Hh + HO_WFHI, Hh + HO_WFLO, Hh + HO_XCW, 256, 256, 384, 384);
    // 10. T2[z] = cinv1 * (H^T[z] @ Xcw)
    hgemm_ta<false><<<dim3(3, 16, 4), 256, SMEM_TA>>>(
        Hh + HO_H, Hh + HO_XCW, N, N, 384, NN, 0, 2, S + FO_P, 384, (size_t)N * 384);
    combT_k<<<dim3(N, 3, 2), 128>>>(S + FO_P, S + FO_CI1, Hh + HO_T2, 384);
    // 11. P2 = sum_z a1^T[z] @ T2[z]; Xor = cis*(P2 + (1-dg2s)*Xcw)
    hgemm_ta<true><<<dim3(3, 16, 4), 256, SMEM_TA>>>(
        Hh + HO_A1, Hh + HO_T2, N, N, 384, NN, (size_t)N * 384, 4,
        S + FO_P, 384, (size_t)N * 384);
    comb11_k<<<dim3(N, 3), 128>>>(S + FO_P, Hh + HO_XCW, S + FO_CIS, S + FO_DG2S, S + FO_XOR);
    // 12. y, losses, final
    y_k<<<(NT * NUM_CLASS) / 256, 256>>>(S + FO_XOR, lw, lb, txp, out + 1);
    lossC_k<<<NT / 256, 256>>>(out + 1, tgt, S + FO_PC);
    lossR_k<<<512, 256>>>(S + FO_XOR, X, S + FO_PR);
    final_k<<<1, 256>>>(S + FO_PR, S + FO_PC, out);
}